// round 10
// baseline (speedup 1.0000x reference)
#include <cuda_runtime.h>
#include <cuda_bf16.h>
#include <cfloat>
#include <cstdint>

#define BB 32768
#define AA 16
#define HH 256
#define DD 128
#define KK 2048

// ---------------------------------------------------------------------------
// Globals: plain row-major bf16 weights/codebook (swizzle applied at cp.async)
// ---------------------------------------------------------------------------
__device__ __nv_bfloat16 g_We1b[HH * 64];    // [256][64], k>=16 zero (zero-init)
__device__ __nv_bfloat16 g_We2b[HH * HH];
__device__ __nv_bfloat16 g_We3b[DD * HH];
__device__ __nv_bfloat16 g_Wd1b[HH * DD];
__device__ __nv_bfloat16 g_Wd2b[HH * HH];
__device__ __nv_bfloat16 g_Whb[AA * HH];
__device__ __nv_bfloat16 g_Eb[KK * DD];
__device__ float    g_esq[KK];
__device__ double   g_sums[2];
__device__ unsigned g_ticket;

// smem regions (dynamic, 224KB), 1 CTA/SM, 128 rows/block
#define R1_OFF 0        // 64KB: h1 / d1 ; dist: esq(8K) + Ebuf@16K(32K) + red@48K
#define R2_OFF 65536    // 64KB: h2 / q / d2 ; dist: Ebuf x2
#define R3_OFF 131072   // 64KB: W rotation 3 x 16KB (+ head Wh)
#define R4_OFF 196608   // 32KB: actB / enc
#define SMEM_TOTAL 229376

// ---------------------------------------------------------------------------
__device__ __forceinline__ unsigned su(const void* p) {
    return (unsigned)__cvta_generic_to_shared(p);
}
__device__ __forceinline__ void cp16(unsigned dst, const void* src) {
    asm volatile("cp.async.cg.shared.global [%0], [%1], 16;\n" :: "r"(dst), "l"(src));
}
__device__ __forceinline__ void cpcommit() { asm volatile("cp.async.commit_group;\n"); }
template <int N>
__device__ __forceinline__ void cpwait() { asm volatile("cp.async.wait_group %0;\n" :: "n"(N)); }

__device__ __forceinline__ void ldm4(unsigned addr, unsigned& r0, unsigned& r1,
                                     unsigned& r2, unsigned& r3) {
    asm volatile("ldmatrix.sync.aligned.m8n8.x4.shared.b16 {%0,%1,%2,%3}, [%4];\n"
                 : "=r"(r0), "=r"(r1), "=r"(r2), "=r"(r3) : "r"(addr));
}
__device__ __forceinline__ void mma_bf16(float* c, const unsigned* a,
                                         unsigned b0, unsigned b1) {
    asm volatile(
        "mma.sync.aligned.m16n8k16.row.col.f32.bf16.bf16.f32 "
        "{%0,%1,%2,%3}, {%4,%5,%6,%7}, {%8,%9}, {%0,%1,%2,%3};\n"
        : "+f"(c[0]), "+f"(c[1]), "+f"(c[2]), "+f"(c[3])
        : "r"(a[0]), "r"(a[1]), "r"(a[2]), "r"(a[3]), "r"(b0), "r"(b1));
}
__device__ __forceinline__ unsigned pack_bf16(float a, float b) {
    __nv_bfloat162 h = __floats2bfloat162_rn(a, b);
    return *reinterpret_cast<unsigned*>(&h);
}

__device__ __forceinline__ void block_reduce_add_to(float v, double* target) {
    __shared__ float sbuf[8];
    int lane = threadIdx.x & 31, wid = threadIdx.x >> 5;
#pragma unroll
    for (int o = 16; o; o >>= 1) v += __shfl_xor_sync(0xffffffffu, v, o);
    if (lane == 0) sbuf[wid] = v;
    __syncthreads();
    if (wid == 0) {
        v = (lane < 8) ? sbuf[lane] : 0.0f;
#pragma unroll
        for (int o = 4; o; o >>= 1) v += __shfl_xor_sync(0xffffffffu, v, o);
        if (lane == 0) atomicAdd(target, (double)v);
    }
}

// ---------------------------------------------------------------------------
// prep: fp32 -> bf16 (plain layout), We1 padded to K=64, esq, zero sums/ticket
// ---------------------------------------------------------------------------
__global__ void prep_kernel(const float4* __restrict__ We1, const float4* __restrict__ We2,
                            const float4* __restrict__ We3, const float4* __restrict__ Wd1,
                            const float4* __restrict__ Wd2, const float4* __restrict__ Wh,
                            const float4* __restrict__ E, const float* __restrict__ Ef) {
    int blk = blockIdx.x;
    if (blk < 456) {
        int i = blk * 256 + threadIdx.x;
        const float4* src; uint2* dst; int j, dj;
        if (i < 16384)       { src = We2; dst = (uint2*)g_We2b; j = i;          dj = j; }
        else if (i < 24576)  { src = We3; dst = (uint2*)g_We3b; j = i - 16384;  dj = j; }
        else if (i < 32768)  { src = Wd1; dst = (uint2*)g_Wd1b; j = i - 24576;  dj = j; }
        else if (i < 49152)  { src = Wd2; dst = (uint2*)g_Wd2b; j = i - 32768;  dj = j; }
        else if (i < 114688) { src = E;   dst = (uint2*)g_Eb;   j = i - 49152;  dj = j; }
        else if (i < 115712) { src = We1; dst = (uint2*)g_We1b; j = i - 114688;
                               dj = (j >> 2) * 16 + (j & 3); }
        else                 { src = Wh;  dst = (uint2*)g_Whb;  j = i - 115712; dj = j; }
        float4 v = src[j];
        uint2 p;
        p.x = pack_bf16(v.x, v.y);
        p.y = pack_bf16(v.z, v.w);
        dst[dj] = p;
    } else {
        if (blk == 456 && threadIdx.x < 2) g_sums[threadIdx.x] = 0.0;
        if (blk == 456 && threadIdx.x == 2) g_ticket = 0u;
        int n = (blk - 456) * 256 + threadIdx.x;
        const float4* r = (const float4*)(Ef + (size_t)n * DD);
        float s = 0.0f;
#pragma unroll
        for (int i = 0; i < DD / 4; i++) {
            float4 v = r[i];
            float a = __bfloat162float(__float2bfloat16_rn(v.x));
            float b = __bfloat162float(__float2bfloat16_rn(v.y));
            float c = __bfloat162float(__float2bfloat16_rn(v.z));
            float d = __bfloat162float(__float2bfloat16_rn(v.w));
            s += a * a + b * b + c * c + d * d;
        }
        g_esq[n] = s;
    }
}

// ---------------------------------------------------------------------------
// W chunk issue: 128 rows x 64 k bf16 (16KB), swizzled. One commit group.
// ---------------------------------------------------------------------------
__device__ __forceinline__ void wissue(unsigned dstb, const __nv_bfloat16* Wg,
                                       int K, int kc, int tid) {
    int sn  = tid >> 1;
    int scb = (tid & 1) * 4;
    const __nv_bfloat16* src = Wg + (size_t)sn * K + kc * 64;
#pragma unroll
    for (int i = 0; i < 4; i++) {
        int c = scb + i;
        cp16(dstb + (sn * 8 + (c ^ (sn & 7))) * 16u, src + c * 8);
    }
    cpcommit();
}

// ---------------------------------------------------------------------------
// GEMM stage (256 threads, M=128, BN=128): C = act(A[128xK] @ W[128xK]^T + b)
// 3-buffer W rotation, one sync per chunk, cross-stage prefetch, and
// FRAGMENT SOFTWARE PIPELINE: batch 6 LDSM of ks+1, then 16 HMMA of ks.
// 8 warps: wm=w&3 (32m), wn=w>>2 (64n).
// ---------------------------------------------------------------------------
template <int K>
__device__ __noinline__ void gemm_stage(
    unsigned Aaddr, int ACH,
    const __nv_bfloat16* __restrict__ Wg,
    const float* __restrict__ bias, int n0,
    char* __restrict__ Ys, int NYCH, bool relu,
    unsigned wbase, int& rot)
{
    constexpr int NCH = K / 64;
    const int tid = threadIdx.x;
    const int w = tid >> 5, L = tid & 31;
    const int wm = w & 3, wn = w >> 2;

    wissue(wbase + ((rot) % 3) * 16384u, Wg, K, 0, tid);
    if (NCH > 1) wissue(wbase + ((rot + 1) % 3) * 16384u, Wg, K, 1, tid);

    float acc[2][8][4];
#pragma unroll
    for (int a = 0; a < 2; a++)
#pragma unroll
        for (int b = 0; b < 8; b++)
#pragma unroll
            for (int c = 0; c < 4; c++) acc[a][b][c] = 0.0f;

    unsigned af[2][2][4], bf[2][4][4];
    const int am  = wm * 32 + (L & 15);
    const int amh = am + 16;
    const int bn  = wn * 64 + (L & 7) + ((L >> 4) << 3);

#pragma unroll
    for (int kc = 0; kc < NCH; kc++) {
        if (kc + 1 < NCH) cpwait<1>(); else cpwait<0>();
        __syncthreads();
        if (kc + 2 < NCH)
            wissue(wbase + ((rot + kc + 2) % 3) * 16384u, Wg, K, kc + 2, tid);

        unsigned Bb = wbase + ((rot + kc) % 3) * 16384u;

        // load frags for ks=0
        {
            int ck  = kc * 8 + (L >> 4);
            int ckb = (L >> 3) & 1;
            ldm4(Aaddr + (am  * ACH + ((ck & ~7) | ((ck & 7) ^ (am  & 7)))) * 16u,
                 af[0][0][0], af[0][0][1], af[0][0][2], af[0][0][3]);
            ldm4(Aaddr + (amh * ACH + ((ck & ~7) | ((ck & 7) ^ (amh & 7)))) * 16u,
                 af[0][1][0], af[0][1][1], af[0][1][2], af[0][1][3]);
#pragma unroll
            for (int np = 0; np < 4; np++) {
                int n = bn + np * 16;
                ldm4(Bb + (n * 8 + (ckb ^ (n & 7))) * 16u,
                     bf[0][np][0], bf[0][np][1], bf[0][np][2], bf[0][np][3]);
            }
        }
#pragma unroll
        for (int ks = 0; ks < 4; ks++) {
            const int cur = ks & 1, nxt = cur ^ 1;
            if (ks < 3) {
                int ck  = kc * 8 + (ks + 1) * 2 + (L >> 4);
                int ckb = (ks + 1) * 2 + ((L >> 3) & 1);
                ldm4(Aaddr + (am  * ACH + ((ck & ~7) | ((ck & 7) ^ (am  & 7)))) * 16u,
                     af[nxt][0][0], af[nxt][0][1], af[nxt][0][2], af[nxt][0][3]);
                ldm4(Aaddr + (amh * ACH + ((ck & ~7) | ((ck & 7) ^ (amh & 7)))) * 16u,
                     af[nxt][1][0], af[nxt][1][1], af[nxt][1][2], af[nxt][1][3]);
#pragma unroll
                for (int np = 0; np < 4; np++) {
                    int n = bn + np * 16;
                    ldm4(Bb + (n * 8 + (ckb ^ (n & 7))) * 16u,
                         bf[nxt][np][0], bf[nxt][np][1], bf[nxt][np][2], bf[nxt][np][3]);
                }
            }
#pragma unroll
            for (int np = 0; np < 4; np++)
#pragma unroll
                for (int mt = 0; mt < 2; mt++) {
                    mma_bf16(acc[mt][np * 2 + 0], af[cur][mt], bf[cur][np][0], bf[cur][np][1]);
                    mma_bf16(acc[mt][np * 2 + 1], af[cur][mt], bf[cur][np][2], bf[cur][np][3]);
                }
        }
    }
    rot = (rot + NCH) % 3;

    const int g = L >> 2, q2 = (L & 3) * 2;
#pragma unroll
    for (int mt = 0; mt < 2; mt++) {
#pragma unroll
        for (int nt = 0; nt < 8; nt++) {
            int ng = n0 + wn * 64 + nt * 8 + q2;
            float b0 = __ldg(&bias[ng]), b1 = __ldg(&bias[ng + 1]);
            int c = ng >> 3;
#pragma unroll
            for (int h = 0; h < 2; h++) {
                int m = wm * 32 + mt * 16 + g + 8 * h;
                float v0 = acc[mt][nt][2 * h + 0] + b0;
                float v1 = acc[mt][nt][2 * h + 1] + b1;
                if (relu) { v0 = fmaxf(v0, 0.0f); v1 = fmaxf(v1, 0.0f); }
                int sw = (c & ~7) | ((c & 7) ^ (m & 7));
                *reinterpret_cast<unsigned*>(Ys + (m * NYCH + sw) * 16 + (ng & 7) * 2)
                    = pack_bf16(v0, v1);
            }
        }
    }
}

// ---------------------------------------------------------------------------
// Megakernel (256 threads, 128 rows/block)
// ---------------------------------------------------------------------------
__global__ __launch_bounds__(256, 1)
void mega_kernel(const float* __restrict__ action,
                 const float* __restrict__ be1, const float* __restrict__ be2,
                 const float* __restrict__ be3, const float* __restrict__ E,
                 const float* __restrict__ bd1, const float* __restrict__ bd2,
                 const float* __restrict__ bh, float* __restrict__ out) {
    extern __shared__ char sm[];
    const int tid = threadIdx.x;
    const int w = tid >> 5, L = tid & 31;
    const int wm = w & 3, wn = w >> 2;
    const int r0 = blockIdx.x * 128;

    char* sH1  = sm + R1_OFF;
    char* sH2  = sm + R2_OFF;
    char* sEnc = sm + R4_OFF;
    unsigned wbase = su(sm + R3_OFF);
    float* esq_s = (float*)(sm + R1_OFF);
    float* red_v = (float*)(sm + R1_OFF + 49152);
    int*   red_i = (int*)(sm + R1_OFF + 50176);
    int*   bidx  = (int*)(sm + R1_OFF + 51200);
    int rot = 0;

    // ---- Stage 1: pack action into R4 (swizzled, K padded to 64) ----
    {
        char* sActB = sEnc;
        {
            int m = tid >> 1, hf = tid & 1;
            const float* ap = action + (size_t)(r0 + m) * AA + hf * 8;
            float4 f0 = __ldg((const float4*)ap);
            float4 f1 = __ldg((const float4*)(ap + 4));
            uint4 pk;
            pk.x = pack_bf16(f0.x, f0.y); pk.y = pack_bf16(f0.z, f0.w);
            pk.z = pack_bf16(f1.x, f1.y); pk.w = pack_bf16(f1.z, f1.w);
            *reinterpret_cast<uint4*>(sActB + (m * 8 + (hf ^ (m & 7))) * 16) = pk;
        }
        uint4 z = make_uint4(0, 0, 0, 0);
        for (int idx = tid; idx < 768; idx += 256) {
            int m = idx / 6, c = 2 + idx % 6;
            *reinterpret_cast<uint4*>(sActB + (m * 8 + (c ^ (m & 7))) * 16) = z;
        }
        gemm_stage<64>(su(sActB), 8, g_We1b,            be1, 0,   sH1, 32, true, wbase, rot);
        gemm_stage<64>(su(sActB), 8, g_We1b + 128 * 64, be1, 128, sH1, 32, true, wbase, rot);
    }

    // ---- Stage 2: h2 = relu(h1 @ We2^T + be2) ----
    gemm_stage<256>(su(sH1), 32, g_We2b,             be2, 0,   sH2, 32, true, wbase, rot);
    gemm_stage<256>(su(sH1), 32, g_We2b + 128 * 256, be2, 128, sH2, 32, true, wbase, rot);

    // ---- Stage 3: enc = h2 @ We3^T + be3 -> R4 (128x128, ACH=16) ----
    gemm_stage<256>(su(sH2), 32, g_We3b, be3, 0, sEnc, 16, false, wbase, rot);

    // ---- Stage 4: dist + argmin, 16 E tiles (128 codes each), 3-deep ----
    {
        unsigned eaddr = su(sEnc);
        unsigned eb[3] = { su(sm + R1_OFF + 16384), su(sm + R2_OFF), su(sm + R2_OFF + 32768) };

        __syncthreads();   // stage-3 lagging readers done before E/esq writes
        {
#pragma unroll
            for (int i = 0; i < 2; i++) {
                int idx = tid + i * 256;
                cp16(su(esq_s) + idx * 16u, g_esq + idx * 4);
            }
            const char* src = (const char*)g_Eb;
#pragma unroll
            for (int i = 0; i < 8; i++) {
                int idx = tid + i * 256;
                int n = idx >> 4, c = idx & 15;
                int sw = (c & 8) | ((c & 7) ^ (n & 7));
                cp16(eb[0] + (n * 16 + sw) * 16u, src + n * 256 + c * 16);
            }
            cpcommit();
        }
        {
            const char* src = (const char*)g_Eb + 32768;
#pragma unroll
            for (int i = 0; i < 8; i++) {
                int idx = tid + i * 256;
                int n = idx >> 4, c = idx & 15;
                int sw = (c & 8) | ((c & 7) ^ (n & 7));
                cp16(eb[1] + (n * 16 + sw) * 16u, src + n * 256 + c * 16);
            }
            cpcommit();
        }

        float bestv[4];
        int   besti[4];
#pragma unroll
        for (int i = 0; i < 4; i++) { bestv[i] = FLT_MAX; besti[i] = 0; }

        const int am  = wm * 32 + (L & 15);
        const int amh = am + 16;
        const int bn  = wn * 64 + (L & 7) + ((L >> 4) << 3);

#pragma unroll 1
        for (int t = 0; t < 16; t++) {
            if (t + 1 < 16) cpwait<1>(); else cpwait<0>();
            __syncthreads();
            if (t + 2 < 16) {
                unsigned dstb = eb[(t + 2) % 3];
                const char* src = (const char*)g_Eb + (size_t)(t + 2) * 32768;
#pragma unroll
                for (int i = 0; i < 8; i++) {
                    int idx = tid + i * 256;
                    int n = idx >> 4, c = idx & 15;
                    int sw = (c & 8) | ((c & 7) ^ (n & 7));
                    cp16(dstb + (n * 16 + sw) * 16u, src + n * 256 + c * 16);
                }
                cpcommit();
            }

            unsigned Bb = eb[t % 3];
            float acc[2][8][4];
#pragma unroll
            for (int a = 0; a < 2; a++)
#pragma unroll
                for (int b = 0; b < 8; b++)
#pragma unroll
                    for (int c = 0; c < 4; c++) acc[a][b][c] = 0.0f;

            unsigned af[2][2][4], bf[2][4][4];
            // load frags ks=0
            {
                int ck  = (L >> 4);
                int ckb = (L >> 3) & 1;
                int swA0 = (ck & 8) | ((ck & 7) ^ (am & 7));
                int swA1 = (ck & 8) | ((ck & 7) ^ (amh & 7));
                ldm4(eaddr + (am  * 16 + swA0) * 16u, af[0][0][0], af[0][0][1], af[0][0][2], af[0][0][3]);
                ldm4(eaddr + (amh * 16 + swA1) * 16u, af[0][1][0], af[0][1][1], af[0][1][2], af[0][1][3]);
#pragma unroll
                for (int np = 0; np < 4; np++) {
                    int n = bn + np * 16;
                    int sw = (ckb & 8) | ((ckb & 7) ^ (n & 7));
                    ldm4(Bb + (n * 16 + sw) * 16u, bf[0][np][0], bf[0][np][1], bf[0][np][2], bf[0][np][3]);
                }
            }
#pragma unroll
            for (int ks = 0; ks < 8; ks++) {
                const int cur = ks & 1, nxt = cur ^ 1;
                if (ks < 7) {
                    int ck  = (ks + 1) * 2 + (L >> 4);
                    int ckb = (ks + 1) * 2 + ((L >> 3) & 1);
                    int swA0 = (ck & 8) | ((ck & 7) ^ (am & 7));
                    int swA1 = (ck & 8) | ((ck & 7) ^ (amh & 7));
                    ldm4(eaddr + (am  * 16 + swA0) * 16u, af[nxt][0][0], af[nxt][0][1], af[nxt][0][2], af[nxt][0][3]);
                    ldm4(eaddr + (amh * 16 + swA1) * 16u, af[nxt][1][0], af[nxt][1][1], af[nxt][1][2], af[nxt][1][3]);
#pragma unroll
                    for (int np = 0; np < 4; np++) {
                        int n = bn + np * 16;
                        int sw = (ckb & 8) | ((ckb & 7) ^ (n & 7));
                        ldm4(Bb + (n * 16 + sw) * 16u, bf[nxt][np][0], bf[nxt][np][1], bf[nxt][np][2], bf[nxt][np][3]);
                    }
                }
#pragma unroll
                for (int np = 0; np < 4; np++)
#pragma unroll
                    for (int mt = 0; mt < 2; mt++) {
                        mma_bf16(acc[mt][np * 2 + 0], af[cur][mt], bf[cur][np][0], bf[cur][np][1]);
                        mma_bf16(acc[mt][np * 2 + 1], af[cur][mt], bf[cur][np][2], bf[cur][np][3]);
                    }
            }

            const int q2 = (L & 3) * 2;
#pragma unroll
            for (int nt = 0; nt < 8; nt++) {
                int n = t * 128 + wn * 64 + nt * 8 + q2;
                float es0 = esq_s[n];
                float es1 = esq_s[n + 1];
#pragma unroll
                for (int mt = 0; mt < 2; mt++) {
#pragma unroll
                    for (int h = 0; h < 2; h++) {
                        int r = mt * 2 + h;
                        float v0 = fmaf(-2.0f, acc[mt][nt][2 * h + 0], es0);
                        float v1 = fmaf(-2.0f, acc[mt][nt][2 * h + 1], es1);
                        if (v0 < bestv[r]) { bestv[r] = v0; besti[r] = n; }
                        if (v1 < bestv[r]) { bestv[r] = v1; besti[r] = n + 1; }
                    }
                }
            }
        }
        __syncthreads();

#pragma unroll
        for (int r = 0; r < 4; r++) {
            float v = bestv[r];
            int   ii = besti[r];
#pragma unroll
            for (int o = 1; o <= 2; o <<= 1) {
                float v2 = __shfl_xor_sync(0xffffffffu, v, o);
                int   i2 = __shfl_xor_sync(0xffffffffu, ii, o);
                if (v2 < v || (v2 == v && i2 < ii)) { v = v2; ii = i2; }
            }
            bestv[r] = v; besti[r] = ii;
        }
        if ((L & 3) == 0) {
            int g = L >> 2;
#pragma unroll
            for (int r = 0; r < 4; r++) {
                int mt = r >> 1, h = r & 1;
                int row = wm * 32 + mt * 16 + g + 8 * h;
                red_v[row * 2 + wn] = bestv[r];
                red_i[row * 2 + wn] = besti[r];
            }
        }
        __syncthreads();
        if (tid < 128) {
            float v0 = red_v[tid * 2], v1 = red_v[tid * 2 + 1];
            int i0 = red_i[tid * 2], i1 = red_i[tid * 2 + 1];
            bidx[tid] = (v1 < v0 || (v1 == v0 && i1 < i0)) ? i1 : i0;
        }
        __syncthreads();
    }

    // ---- Stage 5: gather q = E_fp32[idx] -> R2 (swizzled), vq loss ----
    {
        char* sQ = sH2;
        int m = tid >> 1, hf = tid & 1;
        int code = bidx[m];
        const float4* Ep = (const float4*)(E + ((size_t)code << 7) + hf * 64);
        float s = 0.0f;
#pragma unroll
        for (int j = 0; j < 8; j++) {
            int c = hf * 8 + j;
            float4 q0 = __ldg(&Ep[2 * j]);
            float4 q1 = __ldg(&Ep[2 * j + 1]);
            int sw = (c & 8) | ((c & 7) ^ (m & 7));
            uint4 ev = *reinterpret_cast<uint4*>(sEnc + (m * 16 + sw) * 16);
            const __nv_bfloat162* eh = reinterpret_cast<const __nv_bfloat162*>(&ev);
            float2 e0 = __bfloat1622float2(eh[0]);
            float2 e1 = __bfloat1622float2(eh[1]);
            float2 e2 = __bfloat1622float2(eh[2]);
            float2 e3 = __bfloat1622float2(eh[3]);
            float d;
            d = e0.x - q0.x; s += d * d;  d = e0.y - q0.y; s += d * d;
            d = e1.x - q0.z; s += d * d;  d = e1.y - q0.w; s += d * d;
            d = e2.x - q1.x; s += d * d;  d = e2.y - q1.y; s += d * d;
            d = e3.x - q1.z; s += d * d;  d = e3.y - q1.w; s += d * d;
            uint4 pk;
            pk.x = pack_bf16(q0.x, q0.y); pk.y = pack_bf16(q0.z, q0.w);
            pk.z = pack_bf16(q1.x, q1.y); pk.w = pack_bf16(q1.z, q1.w);
            *reinterpret_cast<uint4*>(sQ + (m * 16 + sw) * 16) = pk;
        }
        block_reduce_add_to(s, &g_sums[0]);
    }

    // ---- Stage 6: d1 = relu(q @ Wd1^T + bd1): R2 -> R1 ----
    gemm_stage<128>(su(sH2), 16, g_Wd1b,             bd1, 0,   sH1, 32, true, wbase, rot);
    gemm_stage<128>(su(sH2), 16, g_Wd1b + 128 * 128, bd1, 128, sH1, 32, true, wbase, rot);

    // ---- Stage 7: d2 = relu(d1 @ Wd2^T + bd2): R1 -> R2 ----
    gemm_stage<256>(su(sH1), 32, g_Wd2b,             bd2, 0,   sH2, 32, true, wbase, rot);
    gemm_stage<256>(su(sH1), 32, g_Wd2b + 128 * 256, bd2, 128, sH2, 32, true, wbase, rot);

    // ---- Stage 8: head = tanh(d2 @ Wh^T + bh), recons loss ----
    {
        unsigned whaddr = wbase + (rot % 3) * 16384u;   // 16x256 bf16 swizzled (8KB)
#pragma unroll
        for (int i = 0; i < 2; i++) {
            int idx = tid * 2 + i;
            int n = idx >> 5, c = idx & 31;
            int sw = (c & 24) | ((c & 7) ^ (n & 7));
            cp16(whaddr + (n * 32 + sw) * 16u, g_Whb + (size_t)n * HH + c * 8);
        }
        cpcommit(); cpwait<0>();
        __syncthreads();

        float s = 0.0f;
        {
            unsigned daddr = su(sH2);
            int mrow = w * 16;   // 8 warps x 16 rows = 128
            float acc[2][4];
#pragma unroll
            for (int a = 0; a < 2; a++)
#pragma unroll
                for (int c = 0; c < 4; c++) acc[a][c] = 0.0f;

            unsigned afh[4], bfh[4];
#pragma unroll
            for (int ks = 0; ks < 16; ks++) {
                int m  = mrow + (L & 15);
                int ck = ks * 2 + (L >> 4);
                int sw = (ck & 24) | ((ck & 7) ^ (m & 7));
                ldm4(daddr + (m * 32 + sw) * 16u, afh[0], afh[1], afh[2], afh[3]);
                int n   = (L & 7) + ((L >> 4) << 3);
                int ckb = ks * 2 + ((L >> 3) & 1);
                int swb = (ckb & 24) | ((ckb & 7) ^ (n & 7));
                ldm4(whaddr + (n * 32 + swb) * 16u, bfh[0], bfh[1], bfh[2], bfh[3]);
                mma_bf16(acc[0], afh, bfh[0], bfh[1]);
                mma_bf16(acc[1], afh, bfh[2], bfh[3]);
            }

            const int g = L >> 2, q2 = (L & 3) * 2;
#pragma unroll
            for (int nt = 0; nt < 2; nt++) {
                int n = nt * 8 + q2;
                float b0 = __ldg(&bh[n]), b1 = __ldg(&bh[n + 1]);
#pragma unroll
                for (int h = 0; h < 2; h++) {
                    int m = mrow + g + 8 * h;
                    const float* ar = action + (size_t)(r0 + m) * AA + n;
                    float t0 = tanhf(acc[nt][2 * h + 0] + b0) - __ldg(&ar[0]);
                    float t1 = tanhf(acc[nt][2 * h + 1] + b1) - __ldg(&ar[1]);
                    s += t0 * t0 + t1 * t1;
                }
            }
        }
        block_reduce_add_to(s, &g_sums[1]);
    }

    // ---- fused finalize ----
    if (tid == 0) {
        __threadfence();
        unsigned t = atomicAdd(&g_ticket, 1u);
        if (t == gridDim.x - 1) {
            double vq  = g_sums[0] / ((double)BB * (double)DD);
            double rec = g_sums[1] / ((double)BB * (double)AA);
            out[0] = (float)(rec + 1.25 * vq);
        }
    }
}

// ---------------------------------------------------------------------------
extern "C" void kernel_launch(void* const* d_in, const int* in_sizes, int n_in,
                              void* d_out, int out_size) {
    const float* action = (const float*)d_in[0];
    const float* We1    = (const float*)d_in[1];
    const float* be1    = (const float*)d_in[2];
    const float* We2    = (const float*)d_in[3];
    const float* be2    = (const float*)d_in[4];
    const float* We3    = (const float*)d_in[5];
    const float* be3    = (const float*)d_in[6];
    const float* E      = (const float*)d_in[7];
    const float* Wd1    = (const float*)d_in[8];
    const float* bd1    = (const float*)d_in[9];
    const float* Wd2    = (const float*)d_in[10];
    const float* bd2    = (const float*)d_in[11];
    const float* Wh     = (const float*)d_in[12];
    const float* bh     = (const float*)d_in[13];
    float* out = (float*)d_out;

    cudaFuncSetAttribute((const void*)mega_kernel,
                         cudaFuncAttributeMaxDynamicSharedMemorySize, SMEM_TOTAL);

    prep_kernel<<<464, 256>>>((const float4*)We1, (const float4*)We2,
                              (const float4*)We3, (const float4*)Wd1,
                              (const float4*)Wd2, (const float4*)Wh,
                              (const float4*)E, E);
    mega_kernel<<<BB / 128, 256, SMEM_TOTAL>>>(action, be1, be2, be3, E,
                                               bd1, bd2, bh, out);
}

// round 11
// speedup vs baseline: 1.0024x; 1.0024x over previous
#include <cuda_runtime.h>
#include <cuda_bf16.h>
#include <cfloat>
#include <cstdint>

#define BB 32768
#define AA 16
#define HH 256
#define DD 128
#define KK 2048

// ---------------------------------------------------------------------------
// Globals: plain row-major bf16 weights/codebook (swizzle applied at cp.async)
// ---------------------------------------------------------------------------
__device__ __nv_bfloat16 g_We1b[HH * 64];    // [256][64], k>=16 zero (zero-init)
__device__ __nv_bfloat16 g_We2b[HH * HH];
__device__ __nv_bfloat16 g_We3b[DD * HH];
__device__ __nv_bfloat16 g_Wd1b[HH * DD];
__device__ __nv_bfloat16 g_Wd2b[HH * HH];
__device__ __nv_bfloat16 g_Whb[AA * HH];
__device__ __nv_bfloat16 g_Eb[KK * DD];
__device__ float    g_esq[KK];
__device__ double   g_sums[2];
__device__ unsigned g_ticket;

// smem regions (dynamic, 224KB), 1 CTA/SM, 128 rows/block
#define R1_OFF 0        // 64KB: h1 / d1 ; dist: esq(8K) + Ebuf@16K(32K) + red@48K
#define R2_OFF 65536    // 64KB: h2 / q / d2 ; dist: Ebuf x2
#define R3_OFF 131072   // 64KB: W rotation 3 x 16KB (+ head Wh)
#define R4_OFF 196608   // 32KB: actB / enc
#define SMEM_TOTAL 229376

// ---------------------------------------------------------------------------
__device__ __forceinline__ unsigned su(const void* p) {
    return (unsigned)__cvta_generic_to_shared(p);
}
__device__ __forceinline__ void cp16(unsigned dst, const void* src) {
    asm volatile("cp.async.cg.shared.global [%0], [%1], 16;\n" :: "r"(dst), "l"(src));
}
__device__ __forceinline__ void cpcommit() { asm volatile("cp.async.commit_group;\n"); }
template <int N>
__device__ __forceinline__ void cpwait() { asm volatile("cp.async.wait_group %0;\n" :: "n"(N)); }

__device__ __forceinline__ void ldm4(unsigned addr, unsigned& r0, unsigned& r1,
                                     unsigned& r2, unsigned& r3) {
    asm volatile("ldmatrix.sync.aligned.m8n8.x4.shared.b16 {%0,%1,%2,%3}, [%4];\n"
                 : "=r"(r0), "=r"(r1), "=r"(r2), "=r"(r3) : "r"(addr));
}
__device__ __forceinline__ void mma_bf16(float* c, const unsigned* a,
                                         unsigned b0, unsigned b1) {
    asm volatile(
        "mma.sync.aligned.m16n8k16.row.col.f32.bf16.bf16.f32 "
        "{%0,%1,%2,%3}, {%4,%5,%6,%7}, {%8,%9}, {%0,%1,%2,%3};\n"
        : "+f"(c[0]), "+f"(c[1]), "+f"(c[2]), "+f"(c[3])
        : "r"(a[0]), "r"(a[1]), "r"(a[2]), "r"(a[3]), "r"(b0), "r"(b1));
}
__device__ __forceinline__ unsigned pack_bf16(float a, float b) {
    __nv_bfloat162 h = __floats2bfloat162_rn(a, b);
    return *reinterpret_cast<unsigned*>(&h);
}

__device__ __forceinline__ void block_reduce_add_to(float v, double* target) {
    __shared__ float sbuf[8];
    int lane = threadIdx.x & 31, wid = threadIdx.x >> 5;
#pragma unroll
    for (int o = 16; o; o >>= 1) v += __shfl_xor_sync(0xffffffffu, v, o);
    if (lane == 0) sbuf[wid] = v;
    __syncthreads();
    if (wid == 0) {
        v = (lane < 8) ? sbuf[lane] : 0.0f;
#pragma unroll
        for (int o = 4; o; o >>= 1) v += __shfl_xor_sync(0xffffffffu, v, o);
        if (lane == 0) atomicAdd(target, (double)v);
    }
}

// ---------------------------------------------------------------------------
// prep: fp32 -> bf16 (plain layout), We1 padded to K=64, esq, zero sums/ticket
// ---------------------------------------------------------------------------
__global__ void prep_kernel(const float4* __restrict__ We1, const float4* __restrict__ We2,
                            const float4* __restrict__ We3, const float4* __restrict__ Wd1,
                            const float4* __restrict__ Wd2, const float4* __restrict__ Wh,
                            const float4* __restrict__ E, const float* __restrict__ Ef) {
    int blk = blockIdx.x;
    if (blk < 456) {
        int i = blk * 256 + threadIdx.x;
        const float4* src; uint2* dst; int j, dj;
        if (i < 16384)       { src = We2; dst = (uint2*)g_We2b; j = i;          dj = j; }
        else if (i < 24576)  { src = We3; dst = (uint2*)g_We3b; j = i - 16384;  dj = j; }
        else if (i < 32768)  { src = Wd1; dst = (uint2*)g_Wd1b; j = i - 24576;  dj = j; }
        else if (i < 49152)  { src = Wd2; dst = (uint2*)g_Wd2b; j = i - 32768;  dj = j; }
        else if (i < 114688) { src = E;   dst = (uint2*)g_Eb;   j = i - 49152;  dj = j; }
        else if (i < 115712) { src = We1; dst = (uint2*)g_We1b; j = i - 114688;
                               dj = (j >> 2) * 16 + (j & 3); }
        else                 { src = Wh;  dst = (uint2*)g_Whb;  j = i - 115712; dj = j; }
        float4 v = src[j];
        uint2 p;
        p.x = pack_bf16(v.x, v.y);
        p.y = pack_bf16(v.z, v.w);
        dst[dj] = p;
    } else {
        if (blk == 456 && threadIdx.x < 2) g_sums[threadIdx.x] = 0.0;
        if (blk == 456 && threadIdx.x == 2) g_ticket = 0u;
        int n = (blk - 456) * 256 + threadIdx.x;
        const float4* r = (const float4*)(Ef + (size_t)n * DD);
        float s = 0.0f;
#pragma unroll
        for (int i = 0; i < DD / 4; i++) {
            float4 v = r[i];
            float a = __bfloat162float(__float2bfloat16_rn(v.x));
            float b = __bfloat162float(__float2bfloat16_rn(v.y));
            float c = __bfloat162float(__float2bfloat16_rn(v.z));
            float d = __bfloat162float(__float2bfloat16_rn(v.w));
            s += a * a + b * b + c * c + d * d;
        }
        g_esq[n] = s;
    }
}

// ---------------------------------------------------------------------------
// W chunk issue: 128 rows x 64 k bf16 (16KB), swizzled. One commit group.
// ---------------------------------------------------------------------------
__device__ __forceinline__ void wissue(unsigned dstb, const __nv_bfloat16* Wg,
                                       int K, int kc, int tid) {
    int sn  = tid >> 1;
    int scb = (tid & 1) * 4;
    const __nv_bfloat16* src = Wg + (size_t)sn * K + kc * 64;
#pragma unroll
    for (int i = 0; i < 4; i++) {
        int c = scb + i;
        cp16(dstb + (sn * 8 + (c ^ (sn & 7))) * 16u, src + c * 8);
    }
    cpcommit();
}

// ---------------------------------------------------------------------------
// GEMM stage (256 threads, M=128, BN=128): C = act(A[128xK] @ W[128xK]^T + b)
// 3-buffer W rotation, one sync per chunk, cross-stage prefetch, fragment
// software pipeline. 8 warps: wm=w&3 (32m), wn=w>>2 (64n).
// ---------------------------------------------------------------------------
template <int K>
__device__ __noinline__ void gemm_stage(
    unsigned Aaddr, int ACH,
    const __nv_bfloat16* __restrict__ Wg,
    const float* __restrict__ bias, int n0,
    char* __restrict__ Ys, int NYCH, bool relu,
    unsigned wbase, int& rot)
{
    constexpr int NCH = K / 64;
    const int tid = threadIdx.x;
    const int w = tid >> 5, L = tid & 31;
    const int wm = w & 3, wn = w >> 2;

    wissue(wbase + ((rot) % 3) * 16384u, Wg, K, 0, tid);
    if (NCH > 1) wissue(wbase + ((rot + 1) % 3) * 16384u, Wg, K, 1, tid);

    float acc[2][8][4];
#pragma unroll
    for (int a = 0; a < 2; a++)
#pragma unroll
        for (int b = 0; b < 8; b++)
#pragma unroll
            for (int c = 0; c < 4; c++) acc[a][b][c] = 0.0f;

    unsigned af[2][2][4], bf[2][4][4];
    const int am  = wm * 32 + (L & 15);
    const int amh = am + 16;
    const int bn  = wn * 64 + (L & 7) + ((L >> 4) << 3);

#pragma unroll
    for (int kc = 0; kc < NCH; kc++) {
        if (kc + 1 < NCH) cpwait<1>(); else cpwait<0>();
        __syncthreads();
        if (kc + 2 < NCH)
            wissue(wbase + ((rot + kc + 2) % 3) * 16384u, Wg, K, kc + 2, tid);

        unsigned Bb = wbase + ((rot + kc) % 3) * 16384u;

        // load frags for ks=0
        {
            int ck  = kc * 8 + (L >> 4);
            int ckb = (L >> 3) & 1;
            ldm4(Aaddr + (am  * ACH + ((ck & ~7) | ((ck & 7) ^ (am  & 7)))) * 16u,
                 af[0][0][0], af[0][0][1], af[0][0][2], af[0][0][3]);
            ldm4(Aaddr + (amh * ACH + ((ck & ~7) | ((ck & 7) ^ (amh & 7)))) * 16u,
                 af[0][1][0], af[0][1][1], af[0][1][2], af[0][1][3]);
#pragma unroll
            for (int np = 0; np < 4; np++) {
                int n = bn + np * 16;
                ldm4(Bb + (n * 8 + (ckb ^ (n & 7))) * 16u,
                     bf[0][np][0], bf[0][np][1], bf[0][np][2], bf[0][np][3]);
            }
        }
#pragma unroll
        for (int ks = 0; ks < 4; ks++) {
            const int cur = ks & 1, nxt = cur ^ 1;
            if (ks < 3) {
                int ck  = kc * 8 + (ks + 1) * 2 + (L >> 4);
                int ckb = (ks + 1) * 2 + ((L >> 3) & 1);
                ldm4(Aaddr + (am  * ACH + ((ck & ~7) | ((ck & 7) ^ (am  & 7)))) * 16u,
                     af[nxt][0][0], af[nxt][0][1], af[nxt][0][2], af[nxt][0][3]);
                ldm4(Aaddr + (amh * ACH + ((ck & ~7) | ((ck & 7) ^ (amh & 7)))) * 16u,
                     af[nxt][1][0], af[nxt][1][1], af[nxt][1][2], af[nxt][1][3]);
#pragma unroll
                for (int np = 0; np < 4; np++) {
                    int n = bn + np * 16;
                    ldm4(Bb + (n * 8 + (ckb ^ (n & 7))) * 16u,
                         bf[nxt][np][0], bf[nxt][np][1], bf[nxt][np][2], bf[nxt][np][3]);
                }
            }
#pragma unroll
            for (int np = 0; np < 4; np++)
#pragma unroll
                for (int mt = 0; mt < 2; mt++) {
                    mma_bf16(acc[mt][np * 2 + 0], af[cur][mt], bf[cur][np][0], bf[cur][np][1]);
                    mma_bf16(acc[mt][np * 2 + 1], af[cur][mt], bf[cur][np][2], bf[cur][np][3]);
                }
        }
    }
    rot = (rot + NCH) % 3;

    const int g = L >> 2, q2 = (L & 3) * 2;
#pragma unroll
    for (int mt = 0; mt < 2; mt++) {
#pragma unroll
        for (int nt = 0; nt < 8; nt++) {
            int ng = n0 + wn * 64 + nt * 8 + q2;
            float b0 = __ldg(&bias[ng]), b1 = __ldg(&bias[ng + 1]);
            int c = ng >> 3;
#pragma unroll
            for (int h = 0; h < 2; h++) {
                int m = wm * 32 + mt * 16 + g + 8 * h;
                float v0 = acc[mt][nt][2 * h + 0] + b0;
                float v1 = acc[mt][nt][2 * h + 1] + b1;
                if (relu) { v0 = fmaxf(v0, 0.0f); v1 = fmaxf(v1, 0.0f); }
                int sw = (c & ~7) | ((c & 7) ^ (m & 7));
                *reinterpret_cast<unsigned*>(Ys + (m * NYCH + sw) * 16 + (ng & 7) * 2)
                    = pack_bf16(v0, v1);
            }
        }
    }
}

// ---------------------------------------------------------------------------
// Megakernel (256 threads, 128 rows/block)
// ---------------------------------------------------------------------------
__global__ __launch_bounds__(256, 1)
void mega_kernel(const float* __restrict__ action,
                 const float* __restrict__ be1, const float* __restrict__ be2,
                 const float* __restrict__ be3, const float* __restrict__ E,
                 const float* __restrict__ bd1, const float* __restrict__ bd2,
                 const float* __restrict__ bh, float* __restrict__ out) {
    extern __shared__ char sm[];
    const int tid = threadIdx.x;
    const int w = tid >> 5, L = tid & 31;
    const int wm = w & 3, wn = w >> 2;
    const int r0 = blockIdx.x * 128;

    char* sH1  = sm + R1_OFF;
    char* sH2  = sm + R2_OFF;
    char* sEnc = sm + R4_OFF;
    unsigned wbase = su(sm + R3_OFF);
    float* esq_s = (float*)(sm + R1_OFF);
    float* red_v = (float*)(sm + R1_OFF + 49152);
    int*   red_i = (int*)(sm + R1_OFF + 50176);
    int*   bidx  = (int*)(sm + R1_OFF + 51200);
    int rot = 0;

    // ---- Stage 1: pack action into R4 (swizzled, K padded to 64) ----
    {
        char* sActB = sEnc;
        {
            int m = tid >> 1, hf = tid & 1;
            const float* ap = action + (size_t)(r0 + m) * AA + hf * 8;
            float4 f0 = __ldg((const float4*)ap);
            float4 f1 = __ldg((const float4*)(ap + 4));
            uint4 pk;
            pk.x = pack_bf16(f0.x, f0.y); pk.y = pack_bf16(f0.z, f0.w);
            pk.z = pack_bf16(f1.x, f1.y); pk.w = pack_bf16(f1.z, f1.w);
            *reinterpret_cast<uint4*>(sActB + (m * 8 + (hf ^ (m & 7))) * 16) = pk;
        }
        uint4 z = make_uint4(0, 0, 0, 0);
        for (int idx = tid; idx < 768; idx += 256) {
            int m = idx / 6, c = 2 + idx % 6;
            *reinterpret_cast<uint4*>(sActB + (m * 8 + (c ^ (m & 7))) * 16) = z;
        }
        gemm_stage<64>(su(sActB), 8, g_We1b,            be1, 0,   sH1, 32, true, wbase, rot);
        gemm_stage<64>(su(sActB), 8, g_We1b + 128 * 64, be1, 128, sH1, 32, true, wbase, rot);
    }

    // ---- Stage 2: h2 = relu(h1 @ We2^T + be2) ----
    gemm_stage<256>(su(sH1), 32, g_We2b,             be2, 0,   sH2, 32, true, wbase, rot);
    gemm_stage<256>(su(sH1), 32, g_We2b + 128 * 256, be2, 128, sH2, 32, true, wbase, rot);

    // ---- Stage 3: enc = h2 @ We3^T + be3 -> R4 (128x128, ACH=16) ----
    gemm_stage<256>(su(sH2), 32, g_We3b, be3, 0, sEnc, 16, false, wbase, rot);

    // ---- Stage 4: dist + argmin, 16 E tiles (128 codes each), 3-deep,
    //      A (enc) fragments cached in registers across all tiles ----
    {
        unsigned eaddr = su(sEnc);
        unsigned eb[3] = { su(sm + R1_OFF + 16384), su(sm + R2_OFF), su(sm + R2_OFF + 32768) };

        __syncthreads();   // stage-3 lagging readers done before E/esq writes
        {
#pragma unroll
            for (int i = 0; i < 2; i++) {
                int idx = tid + i * 256;
                cp16(su(esq_s) + idx * 16u, g_esq + idx * 4);
            }
            const char* src = (const char*)g_Eb;
#pragma unroll
            for (int i = 0; i < 8; i++) {
                int idx = tid + i * 256;
                int n = idx >> 4, c = idx & 15;
                int sw = (c & 8) | ((c & 7) ^ (n & 7));
                cp16(eb[0] + (n * 16 + sw) * 16u, src + n * 256 + c * 16);
            }
            cpcommit();
        }
        {
            const char* src = (const char*)g_Eb + 32768;
#pragma unroll
            for (int i = 0; i < 8; i++) {
                int idx = tid + i * 256;
                int n = idx >> 4, c = idx & 15;
                int sw = (c & 8) | ((c & 7) ^ (n & 7));
                cp16(eb[1] + (n * 16 + sw) * 16u, src + n * 256 + c * 16);
            }
            cpcommit();
        }

        const int am  = wm * 32 + (L & 15);
        const int amh = am + 16;
        const int bn  = wn * 64 + (L & 7) + ((L >> 4) << 3);

        // Cache all A (enc) fragments: 8 ks x 2 mt, overlapped with E cp.async
        unsigned afc[8][2][4];
#pragma unroll
        for (int ks = 0; ks < 8; ks++) {
            int ck  = ks * 2 + (L >> 4);
            int swA0 = (ck & 8) | ((ck & 7) ^ (am & 7));
            int swA1 = (ck & 8) | ((ck & 7) ^ (amh & 7));
            ldm4(eaddr + (am  * 16 + swA0) * 16u,
                 afc[ks][0][0], afc[ks][0][1], afc[ks][0][2], afc[ks][0][3]);
            ldm4(eaddr + (amh * 16 + swA1) * 16u,
                 afc[ks][1][0], afc[ks][1][1], afc[ks][1][2], afc[ks][1][3]);
        }

        float bestv[4];
        int   besti[4];
#pragma unroll
        for (int i = 0; i < 4; i++) { bestv[i] = FLT_MAX; besti[i] = 0; }

#pragma unroll 1
        for (int t = 0; t < 16; t++) {
            if (t + 1 < 16) cpwait<1>(); else cpwait<0>();
            __syncthreads();
            if (t + 2 < 16) {
                unsigned dstb = eb[(t + 2) % 3];
                const char* src = (const char*)g_Eb + (size_t)(t + 2) * 32768;
#pragma unroll
                for (int i = 0; i < 8; i++) {
                    int idx = tid + i * 256;
                    int n = idx >> 4, c = idx & 15;
                    int sw = (c & 8) | ((c & 7) ^ (n & 7));
                    cp16(dstb + (n * 16 + sw) * 16u, src + n * 256 + c * 16);
                }
                cpcommit();
            }

            unsigned Bb = eb[t % 3];
            float acc[2][8][4];
#pragma unroll
            for (int a = 0; a < 2; a++)
#pragma unroll
                for (int b = 0; b < 8; b++)
#pragma unroll
                    for (int c = 0; c < 4; c++) acc[a][b][c] = 0.0f;

#pragma unroll
            for (int ks = 0; ks < 8; ks++) {
                unsigned bf[4][4];
                int ckb = ks * 2 + ((L >> 3) & 1);
#pragma unroll
                for (int np = 0; np < 4; np++) {
                    int n = bn + np * 16;
                    int sw = (ckb & 8) | ((ckb & 7) ^ (n & 7));
                    ldm4(Bb + (n * 16 + sw) * 16u, bf[np][0], bf[np][1], bf[np][2], bf[np][3]);
                }
#pragma unroll
                for (int np = 0; np < 4; np++)
#pragma unroll
                    for (int mt = 0; mt < 2; mt++) {
                        mma_bf16(acc[mt][np * 2 + 0], afc[ks][mt], bf[np][0], bf[np][1]);
                        mma_bf16(acc[mt][np * 2 + 1], afc[ks][mt], bf[np][2], bf[np][3]);
                    }
            }

            const int q2 = (L & 3) * 2;
#pragma unroll
            for (int nt = 0; nt < 8; nt++) {
                int n = t * 128 + wn * 64 + nt * 8 + q2;
                float es0 = esq_s[n];
                float es1 = esq_s[n + 1];
#pragma unroll
                for (int mt = 0; mt < 2; mt++) {
#pragma unroll
                    for (int h = 0; h < 2; h++) {
                        int r = mt * 2 + h;
                        float v0 = fmaf(-2.0f, acc[mt][nt][2 * h + 0], es0);
                        float v1 = fmaf(-2.0f, acc[mt][nt][2 * h + 1], es1);
                        if (v0 < bestv[r]) { bestv[r] = v0; besti[r] = n; }
                        if (v1 < bestv[r]) { bestv[r] = v1; besti[r] = n + 1; }
                    }
                }
            }
        }
        __syncthreads();

#pragma unroll
        for (int r = 0; r < 4; r++) {
            float v = bestv[r];
            int   ii = besti[r];
#pragma unroll
            for (int o = 1; o <= 2; o <<= 1) {
                float v2 = __shfl_xor_sync(0xffffffffu, v, o);
                int   i2 = __shfl_xor_sync(0xffffffffu, ii, o);
                if (v2 < v || (v2 == v && i2 < ii)) { v = v2; ii = i2; }
            }
            bestv[r] = v; besti[r] = ii;
        }
        if ((L & 3) == 0) {
            int g = L >> 2;
#pragma unroll
            for (int r = 0; r < 4; r++) {
                int mt = r >> 1, h = r & 1;
                int row = wm * 32 + mt * 16 + g + 8 * h;
                red_v[row * 2 + wn] = bestv[r];
                red_i[row * 2 + wn] = besti[r];
            }
        }
        __syncthreads();
        if (tid < 128) {
            float v0 = red_v[tid * 2], v1 = red_v[tid * 2 + 1];
            int i0 = red_i[tid * 2], i1 = red_i[tid * 2 + 1];
            bidx[tid] = (v1 < v0 || (v1 == v0 && i1 < i0)) ? i1 : i0;
        }
        __syncthreads();
    }

    // ---- Stage 5: gather q = E_fp32[idx] -> R2 (swizzled), vq loss ----
    {
        char* sQ = sH2;
        int m = tid >> 1, hf = tid & 1;
        int code = bidx[m];
        const float4* Ep = (const float4*)(E + ((size_t)code << 7) + hf * 64);
        float s = 0.0f;
#pragma unroll
        for (int j = 0; j < 8; j++) {
            int c = hf * 8 + j;
            float4 q0 = __ldg(&Ep[2 * j]);
            float4 q1 = __ldg(&Ep[2 * j + 1]);
            int sw = (c & 8) | ((c & 7) ^ (m & 7));
            uint4 ev = *reinterpret_cast<uint4*>(sEnc + (m * 16 + sw) * 16);
            const __nv_bfloat162* eh = reinterpret_cast<const __nv_bfloat162*>(&ev);
            float2 e0 = __bfloat1622float2(eh[0]);
            float2 e1 = __bfloat1622float2(eh[1]);
            float2 e2 = __bfloat1622float2(eh[2]);
            float2 e3 = __bfloat1622float2(eh[3]);
            float d;
            d = e0.x - q0.x; s += d * d;  d = e0.y - q0.y; s += d * d;
            d = e1.x - q0.z; s += d * d;  d = e1.y - q0.w; s += d * d;
            d = e2.x - q1.x; s += d * d;  d = e2.y - q1.y; s += d * d;
            d = e3.x - q1.z; s += d * d;  d = e3.y - q1.w; s += d * d;
            uint4 pk;
            pk.x = pack_bf16(q0.x, q0.y); pk.y = pack_bf16(q0.z, q0.w);
            pk.z = pack_bf16(q1.x, q1.y); pk.w = pack_bf16(q1.z, q1.w);
            *reinterpret_cast<uint4*>(sQ + (m * 16 + sw) * 16) = pk;
        }
        block_reduce_add_to(s, &g_sums[0]);
    }

    // ---- Stage 6: d1 = relu(q @ Wd1^T + bd1): R2 -> R1 ----
    gemm_stage<128>(su(sH2), 16, g_Wd1b,             bd1, 0,   sH1, 32, true, wbase, rot);
    gemm_stage<128>(su(sH2), 16, g_Wd1b + 128 * 128, bd1, 128, sH1, 32, true, wbase, rot);

    // ---- Stage 7: d2 = relu(d1 @ Wd2^T + bd2): R1 -> R2 ----
    gemm_stage<256>(su(sH1), 32, g_Wd2b,             bd2, 0,   sH2, 32, true, wbase, rot);
    gemm_stage<256>(su(sH1), 32, g_Wd2b + 128 * 256, bd2, 128, sH2, 32, true, wbase, rot);

    // ---- Stage 8: head = tanh(d2 @ Wh^T + bh), recons loss ----
    {
        unsigned whaddr = wbase + (rot % 3) * 16384u;   // 16x256 bf16 swizzled (8KB)
#pragma unroll
        for (int i = 0; i < 2; i++) {
            int idx = tid * 2 + i;
            int n = idx >> 5, c = idx & 31;
            int sw = (c & 24) | ((c & 7) ^ (n & 7));
            cp16(whaddr + (n * 32 + sw) * 16u, g_Whb + (size_t)n * HH + c * 8);
        }
        cpcommit(); cpwait<0>();
        __syncthreads();

        float s = 0.0f;
        {
            unsigned daddr = su(sH2);
            int mrow = w * 16;   // 8 warps x 16 rows = 128
            float acc[2][4];
#pragma unroll
            for (int a = 0; a < 2; a++)
#pragma unroll
                for (int c = 0; c < 4; c++) acc[a][c] = 0.0f;

            unsigned afh[4], bfh[4];
#pragma unroll
            for (int ks = 0; ks < 16; ks++) {
                int m  = mrow + (L & 15);
                int ck = ks * 2 + (L >> 4);
                int sw = (ck & 24) | ((ck & 7) ^ (m & 7));
                ldm4(daddr + (m * 32 + sw) * 16u, afh[0], afh[1], afh[2], afh[3]);
                int n   = (L & 7) + ((L >> 4) << 3);
                int ckb = ks * 2 + ((L >> 3) & 1);
                int swb = (ckb & 24) | ((ckb & 7) ^ (n & 7));
                ldm4(whaddr + (n * 32 + swb) * 16u, bfh[0], bfh[1], bfh[2], bfh[3]);
                mma_bf16(acc[0], afh, bfh[0], bfh[1]);
                mma_bf16(acc[1], afh, bfh[2], bfh[3]);
            }

            const int g = L >> 2, q2 = (L & 3) * 2;
#pragma unroll
            for (int nt = 0; nt < 2; nt++) {
                int n = nt * 8 + q2;
                float b0 = __ldg(&bh[n]), b1 = __ldg(&bh[n + 1]);
#pragma unroll
                for (int h = 0; h < 2; h++) {
                    int m = mrow + g + 8 * h;
                    const float* ar = action + (size_t)(r0 + m) * AA + n;
                    float t0 = tanhf(acc[nt][2 * h + 0] + b0) - __ldg(&ar[0]);
                    float t1 = tanhf(acc[nt][2 * h + 1] + b1) - __ldg(&ar[1]);
                    s += t0 * t0 + t1 * t1;
                }
            }
        }
        block_reduce_add_to(s, &g_sums[1]);
    }

    // ---- fused finalize ----
    if (tid == 0) {
        __threadfence();
        unsigned t = atomicAdd(&g_ticket, 1u);
        if (t == gridDim.x - 1) {
            double vq  = g_sums[0] / ((double)BB * (double)DD);
            double rec = g_sums[1] / ((double)BB * (double)AA);
            out[0] = (float)(rec + 1.25 * vq);
        }
    }
}

// ---------------------------------------------------------------------------
extern "C" void kernel_launch(void* const* d_in, const int* in_sizes, int n_in,
                              void* d_out, int out_size) {
    const float* action = (const float*)d_in[0];
    const float* We1    = (const float*)d_in[1];
    const float* be1    = (const float*)d_in[2];
    const float* We2    = (const float*)d_in[3];
    const float* be2    = (const float*)d_in[4];
    const float* We3    = (const float*)d_in[5];
    const float* be3    = (const float*)d_in[6];
    const float* E      = (const float*)d_in[7];
    const float* Wd1    = (const float*)d_in[8];
    const float* bd1    = (const float*)d_in[9];
    const float* Wd2    = (const float*)d_in[10];
    const float* bd2    = (const float*)d_in[11];
    const float* Wh     = (const float*)d_in[12];
    const float* bh     = (const float*)d_in[13];
    float* out = (float*)d_out;

    cudaFuncSetAttribute((const void*)mega_kernel,
                         cudaFuncAttributeMaxDynamicSharedMemorySize, SMEM_TOTAL);

    prep_kernel<<<464, 256>>>((const float4*)We1, (const float4*)We2,
                              (const float4*)We3, (const float4*)Wd1,
                              (const float4*)Wd2, (const float4*)Wh,
                              (const float4*)E, E);
    mega_kernel<<<BB / 128, 256, SMEM_TOTAL>>>(action, be1, be2, be3, E,
                                               bd1, bd2, bh, out);
}

// round 12
// speedup vs baseline: 1.0755x; 1.0729x over previous
#include <cuda_runtime.h>
#include <cuda_bf16.h>
#include <cfloat>
#include <cstdint>

#define BB 32768
#define AA 16
#define HH 256
#define DD 128
#define KK 2048

// ---------------------------------------------------------------------------
// Globals: plain row-major bf16 weights/codebook (swizzle applied at cp.async)
// ---------------------------------------------------------------------------
__device__ __nv_bfloat16 g_We1b[HH * 64];    // [256][64], k>=16 zero (zero-init)
__device__ __nv_bfloat16 g_We2b[HH * HH];
__device__ __nv_bfloat16 g_We3b[DD * HH];
__device__ __nv_bfloat16 g_Wd1b[HH * DD];
__device__ __nv_bfloat16 g_Wd2b[HH * HH];
__device__ __nv_bfloat16 g_Whb[AA * HH];
__device__ __nv_bfloat16 g_Eb[KK * DD];
__device__ float    g_esq[KK];
__device__ double   g_sums[2];
__device__ unsigned g_ticket;

// smem regions (dynamic, 224KB)
#define R1_OFF 0        // 64KB: sH1 | (esq/red/bestidx) | sD1
#define R2_OFF 65536    // 64KB: sH2 | sQ | sD2
#define R3_OFF 131072   // 64KB: W double buffer | E double buffer | sWh
#define R4_OFF 196608   // 32KB: sActB | sEnc
#define SMEM_TOTAL 229376

// ---------------------------------------------------------------------------
// Helpers
// ---------------------------------------------------------------------------
__device__ __forceinline__ unsigned su(const void* p) {
    return (unsigned)__cvta_generic_to_shared(p);
}
__device__ __forceinline__ void cp16(unsigned dst, const void* src) {
    asm volatile("cp.async.cg.shared.global [%0], [%1], 16;\n" :: "r"(dst), "l"(src));
}
__device__ __forceinline__ void cpcommit() { asm volatile("cp.async.commit_group;\n"); }
template <int N>
__device__ __forceinline__ void cpwait() { asm volatile("cp.async.wait_group %0;\n" :: "n"(N)); }

__device__ __forceinline__ void ldm4(unsigned addr, unsigned& r0, unsigned& r1,
                                     unsigned& r2, unsigned& r3) {
    asm volatile("ldmatrix.sync.aligned.m8n8.x4.shared.b16 {%0,%1,%2,%3}, [%4];\n"
                 : "=r"(r0), "=r"(r1), "=r"(r2), "=r"(r3) : "r"(addr));
}
__device__ __forceinline__ void mma_bf16(float* c, unsigned a0, unsigned a1, unsigned a2,
                                         unsigned a3, unsigned b0, unsigned b1) {
    asm volatile(
        "mma.sync.aligned.m16n8k16.row.col.f32.bf16.bf16.f32 "
        "{%0,%1,%2,%3}, {%4,%5,%6,%7}, {%8,%9}, {%0,%1,%2,%3};\n"
        : "+f"(c[0]), "+f"(c[1]), "+f"(c[2]), "+f"(c[3])
        : "r"(a0), "r"(a1), "r"(a2), "r"(a3), "r"(b0), "r"(b1));
}
__device__ __forceinline__ unsigned pack_bf16(float a, float b) {
    __nv_bfloat162 h = __floats2bfloat162_rn(a, b);
    return *reinterpret_cast<unsigned*>(&h);
}

__device__ __forceinline__ void block_reduce_add_to(float v, double* target) {
    __shared__ float sbuf[32];
    int lane = threadIdx.x & 31;
    int wid  = threadIdx.x >> 5;
#pragma unroll
    for (int o = 16; o; o >>= 1) v += __shfl_xor_sync(0xffffffffu, v, o);
    if (lane == 0) sbuf[wid] = v;
    __syncthreads();
    if (wid == 0) {
        v = (lane < 8) ? sbuf[lane] : 0.0f;
#pragma unroll
        for (int o = 4; o; o >>= 1) v += __shfl_xor_sync(0xffffffffu, v, o);
        if (lane == 0) atomicAdd(target, (double)v);
    }
}

// ---------------------------------------------------------------------------
// prep: fp32 -> bf16 (plain layout), We1 padded to K=64, esq, zero sums/ticket
// Blocks 0..455: conversion (116736 float4). Blocks 456..463: esq rows.
// ---------------------------------------------------------------------------
__global__ void prep_kernel(const float4* __restrict__ We1, const float4* __restrict__ We2,
                            const float4* __restrict__ We3, const float4* __restrict__ Wd1,
                            const float4* __restrict__ Wd2, const float4* __restrict__ Wh,
                            const float4* __restrict__ E, const float* __restrict__ Ef) {
    int blk = blockIdx.x;
    if (blk < 456) {
        int i = blk * 256 + threadIdx.x;
        const float4* src; uint2* dst; int j, dj;
        if (i < 16384)       { src = We2; dst = (uint2*)g_We2b; j = i;          dj = j; }
        else if (i < 24576)  { src = We3; dst = (uint2*)g_We3b; j = i - 16384;  dj = j; }
        else if (i < 32768)  { src = Wd1; dst = (uint2*)g_Wd1b; j = i - 24576;  dj = j; }
        else if (i < 49152)  { src = Wd2; dst = (uint2*)g_Wd2b; j = i - 32768;  dj = j; }
        else if (i < 114688) { src = E;   dst = (uint2*)g_Eb;   j = i - 49152;  dj = j; }
        else if (i < 115712) { src = We1; dst = (uint2*)g_We1b; j = i - 114688;
                               dj = (j >> 2) * 16 + (j & 3); }
        else                 { src = Wh;  dst = (uint2*)g_Whb;  j = i - 115712; dj = j; }
        float4 v = src[j];
        uint2 p;
        p.x = pack_bf16(v.x, v.y);
        p.y = pack_bf16(v.z, v.w);
        dst[dj] = p;
    } else {
        if (blk == 456 && threadIdx.x < 2) g_sums[threadIdx.x] = 0.0;
        if (blk == 456 && threadIdx.x == 2) g_ticket = 0u;
        int n = (blk - 456) * 256 + threadIdx.x;
        const float4* r = (const float4*)(Ef + (size_t)n * DD);
        float s = 0.0f;
#pragma unroll
        for (int i = 0; i < DD / 4; i++) {
            float4 v = r[i];
            float a = __bfloat162float(__float2bfloat16_rn(v.x));
            float b = __bfloat162float(__float2bfloat16_rn(v.y));
            float c = __bfloat162float(__float2bfloat16_rn(v.z));
            float d = __bfloat162float(__float2bfloat16_rn(v.w));
            s += a * a + b * b + c * c + d * d;
        }
        g_esq[n] = s;
    }
}

// ---------------------------------------------------------------------------
// GEMM stage (256 threads, M=128, BN=128): C = act(A_smem[128xK] @ W[128xK]^T + b)
// W streamed in 64-k chunks (16KB), double-buffered in wbuf (R4 structure).
// 8 warps: wm=w&3 (32m), wn=w>>2 (64n).
// ---------------------------------------------------------------------------
template <int K>
__device__ __noinline__ void gemm_stage(
    unsigned Aaddr, int ACH,
    const __nv_bfloat16* __restrict__ Wg,
    const float* __restrict__ bias, int n0,
    __nv_bfloat16* __restrict__ Ys, int NYCH, bool relu,
    unsigned wbuf)
{
    constexpr int NCH = K / 64;
    const int tid = threadIdx.x;
    const int w = tid >> 5, L = tid & 31;
    const int wm = w & 3, wn = w >> 2;

    float acc[2][8][4];
#pragma unroll
    for (int a = 0; a < 2; a++)
#pragma unroll
        for (int b = 0; b < 8; b++)
#pragma unroll
            for (int c = 0; c < 4; c++) acc[a][b][c] = 0.0f;

    const int sn  = tid >> 1;
    const int scb = (tid & 1) * 4;
    const __nv_bfloat16* Wrow = Wg + (size_t)sn * K;

#pragma unroll
    for (int i = 0; i < 4; i++) {
        int c = scb + i;
        cp16(wbuf + (sn * 8 + (c ^ (sn & 7))) * 16u, Wrow + c * 8);
    }
    cpcommit();

    for (int kc = 0; kc < NCH; kc++) {
        if (kc + 1 < NCH) {
            unsigned dstb = wbuf + ((kc + 1) & 1) * 16384u;
            const __nv_bfloat16* src = Wrow + (kc + 1) * 64;
#pragma unroll
            for (int i = 0; i < 4; i++) {
                int c = scb + i;
                cp16(dstb + (sn * 8 + (c ^ (sn & 7))) * 16u, src + c * 8);
            }
            cpcommit();
            cpwait<1>();
        } else {
            cpwait<0>();
        }
        __syncthreads();

        unsigned Bb = wbuf + (kc & 1) * 16384u;
#pragma unroll
        for (int ks = 0; ks < 4; ks++) {
            unsigned a[2][4];
#pragma unroll
            for (int mt = 0; mt < 2; mt++) {
                int m  = wm * 32 + mt * 16 + (L & 15);
                int ck = kc * 8 + ks * 2 + (L >> 4);
                int sw = (ck & ~7) | ((ck & 7) ^ (m & 7));
                ldm4(Aaddr + (m * ACH + sw) * 16u, a[mt][0], a[mt][1], a[mt][2], a[mt][3]);
            }
#pragma unroll
            for (int np = 0; np < 4; np++) {
                int n   = wn * 64 + np * 16 + (L & 7) + ((L >> 4) << 3);
                int ckb = ks * 2 + ((L >> 3) & 1);
                unsigned b0, b1, b2, b3;
                ldm4(Bb + (n * 8 + (ckb ^ (n & 7))) * 16u, b0, b1, b2, b3);
#pragma unroll
                for (int mt = 0; mt < 2; mt++) {
                    mma_bf16(acc[mt][np * 2 + 0], a[mt][0], a[mt][1], a[mt][2], a[mt][3], b0, b1);
                    mma_bf16(acc[mt][np * 2 + 1], a[mt][0], a[mt][1], a[mt][2], a[mt][3], b2, b3);
                }
            }
        }
        __syncthreads();
    }

    const int g = L >> 2, q2 = (L & 3) * 2;
#pragma unroll
    for (int mt = 0; mt < 2; mt++) {
#pragma unroll
        for (int nt = 0; nt < 8; nt++) {
            int ng = n0 + wn * 64 + nt * 8 + q2;
            float b0 = __ldg(&bias[ng]), b1 = __ldg(&bias[ng + 1]);
            int c  = ng >> 3;
#pragma unroll
            for (int h = 0; h < 2; h++) {
                int m = wm * 32 + mt * 16 + g + 8 * h;
                float v0 = acc[mt][nt][2 * h + 0] + b0;
                float v1 = acc[mt][nt][2 * h + 1] + b1;
                if (relu) { v0 = fmaxf(v0, 0.0f); v1 = fmaxf(v1, 0.0f); }
                int sw = (c & ~7) | ((c & 7) ^ (m & 7));
                *reinterpret_cast<unsigned*>(
                    reinterpret_cast<char*>(Ys) + (m * NYCH + sw) * 16 + (ng & 7) * 2)
                    = pack_bf16(v0, v1);
            }
        }
    }
}

// ---------------------------------------------------------------------------
// Megakernel: per block, 128 rows end-to-end (exact R4 structure + ticket).
// ---------------------------------------------------------------------------
__global__ __launch_bounds__(256, 1)
void mega_kernel(const float* __restrict__ action,
                 const float* __restrict__ be1, const float* __restrict__ be2,
                 const float* __restrict__ be3, const float* __restrict__ E,
                 const float* __restrict__ bd1, const float* __restrict__ bd2,
                 const float* __restrict__ bh, float* __restrict__ out) {
    extern __shared__ char sm[];
    const int tid = threadIdx.x;
    const int w = tid >> 5, L = tid & 31;
    const int wm = w & 3, wn = w >> 2;
    const int r0 = blockIdx.x * 128;

    __nv_bfloat16* sH1  = (__nv_bfloat16*)(sm + R1_OFF);
    __nv_bfloat16* sD1  = (__nv_bfloat16*)(sm + R1_OFF);
    __nv_bfloat16* sH2  = (__nv_bfloat16*)(sm + R2_OFF);
    __nv_bfloat16* sQ   = (__nv_bfloat16*)(sm + R2_OFF);
    __nv_bfloat16* sD2  = (__nv_bfloat16*)(sm + R2_OFF);
    __nv_bfloat16* sEnc = (__nv_bfloat16*)(sm + R4_OFF);
    float* sEsq    = (float*)(sm + R1_OFF);
    float* red_v   = (float*)(sm + R1_OFF + 8192);
    int*   red_i   = (int*)  (sm + R1_OFF + 10240);
    int*   bestidx = (int*)  (sm + R1_OFF + 12288);

    // ---- Stage 1: h1 = relu(action @ We1^T + be1) ----
    {
        char* sActB = sm + R4_OFF;           // 128 x 64 bf16 (k padded), swizzled
        {
            int m = tid >> 1, hf = tid & 1;
            const float* ap = action + (size_t)(r0 + m) * AA + hf * 8;
            float4 f0 = __ldg((const float4*)ap);
            float4 f1 = __ldg((const float4*)(ap + 4));
            uint4 pk;
            pk.x = pack_bf16(f0.x, f0.y); pk.y = pack_bf16(f0.z, f0.w);
            pk.z = pack_bf16(f1.x, f1.y); pk.w = pack_bf16(f1.z, f1.w);
            *reinterpret_cast<uint4*>(sActB + (m * 8 + (hf ^ (m & 7))) * 16) = pk;
        }
        uint4 z = make_uint4(0, 0, 0, 0);
#pragma unroll
        for (int t = 0; t < 3; t++) {
            int idx = tid + t * 256;
            int m = idx / 6, c = 2 + idx % 6;
            *reinterpret_cast<uint4*>(sActB + (m * 8 + (c ^ (m & 7))) * 16) = z;
        }
        __syncthreads();

        unsigned wb = su(sm + R3_OFF + 16384);
        gemm_stage<64>(su(sActB), 8, g_We1b,             be1, 0,   sH1, 32, true, wb);
        gemm_stage<64>(su(sActB), 8, g_We1b + 128 * 64,  be1, 128, sH1, 32, true, wb);
    }
    __syncthreads();

    // ---- Stage 2: h2 = relu(h1 @ We2^T + be2) ----
    {
        unsigned wb = su(sm + R3_OFF);
        gemm_stage<256>(su(sH1), 32, g_We2b,             be2, 0,   sH2, 32, true, wb);
        gemm_stage<256>(su(sH1), 32, g_We2b + 128 * 256, be2, 128, sH2, 32, true, wb);
    }
    __syncthreads();

    // ---- Stage 3: enc = h2 @ We3^T + be3 ----
    gemm_stage<256>(su(sH2), 32, g_We3b, be3, 0, sEnc, 16, false, su(sm + R3_OFF));
    __syncthreads();

    // ---- Stage 4: dist + argmin over 2048 codes ----
    {
        unsigned ebuf = su(sm + R3_OFF);        // 2 x 32KB E tiles
        unsigned eaddr = su(sEnc);

        // group 0: esq + E tile 0
#pragma unroll
        for (int t = 0; t < 2; t++) {
            int idx = tid + t * 256;
            cp16(su(sEsq) + idx * 16u, g_esq + idx * 4);
        }
#pragma unroll
        for (int t = 0; t < 8; t++) {
            int idx = tid + t * 256;
            int n = idx >> 4, c = idx & 15;
            int sw = (c & 8) | ((c & 7) ^ (n & 7));
            cp16(ebuf + (n * 16 + sw) * 16u, (const char*)g_Eb + (size_t)n * 256 + c * 16);
        }
        cpcommit();

        float bestv[4];
        int   besti[4];
#pragma unroll
        for (int i = 0; i < 4; i++) { bestv[i] = FLT_MAX; besti[i] = 0; }

        for (int t0 = 0; t0 < 16; t0++) {
            if (t0 + 1 < 16) {
                unsigned bb = ebuf + ((t0 + 1) & 1) * 32768u;
                const char* Eg = (const char*)g_Eb + (size_t)(t0 + 1) * 32768;
#pragma unroll
                for (int t = 0; t < 8; t++) {
                    int idx = tid + t * 256;
                    int n = idx >> 4, c = idx & 15;
                    int sw = (c & 8) | ((c & 7) ^ (n & 7));
                    cp16(bb + (n * 16 + sw) * 16u, Eg + (size_t)n * 256 + c * 16);
                }
                cpcommit();
                cpwait<1>();
            } else {
                cpwait<0>();
            }
            __syncthreads();

            unsigned Bb = ebuf + (t0 & 1) * 32768u;
            float acc[2][8][4];
#pragma unroll
            for (int a = 0; a < 2; a++)
#pragma unroll
                for (int b = 0; b < 8; b++)
#pragma unroll
                    for (int c = 0; c < 4; c++) acc[a][b][c] = 0.0f;

#pragma unroll
            for (int ks = 0; ks < 8; ks++) {
                unsigned a[2][4];
#pragma unroll
                for (int mt = 0; mt < 2; mt++) {
                    int m  = wm * 32 + mt * 16 + (L & 15);
                    int ck = ks * 2 + (L >> 4);
                    int sw = (ck & 8) | ((ck & 7) ^ (m & 7));
                    ldm4(eaddr + (m * 16 + sw) * 16u, a[mt][0], a[mt][1], a[mt][2], a[mt][3]);
                }
#pragma unroll
                for (int np = 0; np < 4; np++) {
                    int n   = wn * 64 + np * 16 + (L & 7) + ((L >> 4) << 3);
                    int ckb = ks * 2 + ((L >> 3) & 1);
                    int sw  = (ckb & 8) | ((ckb & 7) ^ (n & 7));
                    unsigned b0, b1, b2, b3;
                    ldm4(Bb + (n * 16 + sw) * 16u, b0, b1, b2, b3);
#pragma unroll
                    for (int mt = 0; mt < 2; mt++) {
                        mma_bf16(acc[mt][np * 2 + 0], a[mt][0], a[mt][1], a[mt][2], a[mt][3], b0, b1);
                        mma_bf16(acc[mt][np * 2 + 1], a[mt][0], a[mt][1], a[mt][2], a[mt][3], b2, b3);
                    }
                }
            }

            const int q2 = (L & 3) * 2;
#pragma unroll
            for (int nt = 0; nt < 8; nt++) {
                int n = t0 * 128 + wn * 64 + nt * 8 + q2;
                float es0 = sEsq[n];
                float es1 = sEsq[n + 1];
#pragma unroll
                for (int mt = 0; mt < 2; mt++) {
#pragma unroll
                    for (int h = 0; h < 2; h++) {
                        int r = mt * 2 + h;
                        float v0 = fmaf(-2.0f, acc[mt][nt][2 * h + 0], es0);
                        float v1 = fmaf(-2.0f, acc[mt][nt][2 * h + 1], es1);
                        if (v0 < bestv[r]) { bestv[r] = v0; besti[r] = n; }
                        if (v1 < bestv[r]) { bestv[r] = v1; besti[r] = n + 1; }
                    }
                }
            }
            __syncthreads();
        }

        // quad reduce (lanes sharing the same row)
#pragma unroll
        for (int r = 0; r < 4; r++) {
            float v = bestv[r];
            int   ii = besti[r];
#pragma unroll
            for (int o = 1; o <= 2; o <<= 1) {
                float v2 = __shfl_xor_sync(0xffffffffu, v, o);
                int   i2 = __shfl_xor_sync(0xffffffffu, ii, o);
                if (v2 < v || (v2 == v && i2 < ii)) { v = v2; ii = i2; }
            }
            bestv[r] = v; besti[r] = ii;
        }
        if ((L & 3) == 0) {
            int g = L >> 2;
#pragma unroll
            for (int r = 0; r < 4; r++) {
                int mt = r >> 1, h = r & 1;
                int row = wm * 32 + mt * 16 + g + 8 * h;
                red_v[row * 2 + wn] = bestv[r];
                red_i[row * 2 + wn] = besti[r];
            }
        }
        __syncthreads();
        if (tid < 128) {
            float v0 = red_v[tid * 2], v1 = red_v[tid * 2 + 1];
            int   i0 = red_i[tid * 2], i1 = red_i[tid * 2 + 1];
            bestidx[tid] = (v1 < v0 || (v1 == v0 && i1 < i0)) ? i1 : i0;
        }
        __syncthreads();
    }

    // ---- Stage 5: gather q = E[idx], vq loss ----
    {
        int m = tid >> 1, hf = tid & 1;
        int code = bestidx[m];
        const float4* Ep = reinterpret_cast<const float4*>(E + ((size_t)code << 7) + hf * 64);
        float s = 0.0f;
#pragma unroll
        for (int j = 0; j < 8; j++) {
            int c = hf * 8 + j;
            float4 q0 = __ldg(&Ep[2 * j]);
            float4 q1 = __ldg(&Ep[2 * j + 1]);
            int sw = (c & 8) | ((c & 7) ^ (m & 7));
            uint4 ev = *reinterpret_cast<uint4*>(
                reinterpret_cast<char*>(sEnc) + (m * 16 + sw) * 16);
            const __nv_bfloat162* eh = reinterpret_cast<const __nv_bfloat162*>(&ev);
            float2 e0 = __bfloat1622float2(eh[0]);
            float2 e1 = __bfloat1622float2(eh[1]);
            float2 e2 = __bfloat1622float2(eh[2]);
            float2 e3 = __bfloat1622float2(eh[3]);
            float d;
            d = e0.x - q0.x; s += d * d;  d = e0.y - q0.y; s += d * d;
            d = e1.x - q0.z; s += d * d;  d = e1.y - q0.w; s += d * d;
            d = e2.x - q1.x; s += d * d;  d = e2.y - q1.y; s += d * d;
            d = e3.x - q1.z; s += d * d;  d = e3.y - q1.w; s += d * d;
            uint4 pk;
            pk.x = pack_bf16(q0.x, q0.y); pk.y = pack_bf16(q0.z, q0.w);
            pk.z = pack_bf16(q1.x, q1.y); pk.w = pack_bf16(q1.z, q1.w);
            *reinterpret_cast<uint4*>(
                reinterpret_cast<char*>(sQ) + (m * 16 + sw) * 16) = pk;
        }
        block_reduce_add_to(s, &g_sums[0]);
    }
    __syncthreads();

    // ---- Stage 6/7: decoder ----
    {
        unsigned wb = su(sm + R3_OFF);
        gemm_stage<128>(su(sQ), 16, g_Wd1b,             bd1, 0,   sD1, 32, true, wb);
        gemm_stage<128>(su(sQ), 16, g_Wd1b + 128 * 128, bd1, 128, sD1, 32, true, wb);
        __syncthreads();
        gemm_stage<256>(su(sD1), 32, g_Wd2b,             bd2, 0,   sD2, 32, true, wb);
        gemm_stage<256>(su(sD1), 32, g_Wd2b + 128 * 256, bd2, 128, sD2, 32, true, wb);
    }
    __syncthreads();

    // ---- Stage 8: head mma + tanh + recons loss ----
    {
        unsigned whaddr = su(sm + R3_OFF);     // 16 x 256 bf16 swizzled (8KB)
#pragma unroll
        for (int i = 0; i < 2; i++) {
            int idx = tid * 2 + i;
            int n = idx >> 5, c = idx & 31;
            int sw = (c & 24) | ((c & 7) ^ (n & 7));
            cp16(whaddr + (n * 32 + sw) * 16u, g_Whb + (size_t)n * HH + c * 8);
        }
        cpcommit(); cpwait<0>();
        __syncthreads();

        unsigned daddr = su(sD2);
        float acc[2][4];
#pragma unroll
        for (int a = 0; a < 2; a++)
#pragma unroll
            for (int c = 0; c < 4; c++) acc[a][c] = 0.0f;

#pragma unroll
        for (int ks = 0; ks < 16; ks++) {
            int m  = w * 16 + (L & 15);
            int ck = ks * 2 + (L >> 4);
            int sw = (ck & 24) | ((ck & 7) ^ (m & 7));
            unsigned a0, a1, a2, a3;
            ldm4(daddr + (m * 32 + sw) * 16u, a0, a1, a2, a3);
            int n   = (L & 7) + ((L >> 4) << 3);
            int ckb = ks * 2 + ((L >> 3) & 1);
            int swb = (ckb & 24) | ((ckb & 7) ^ (n & 7));
            unsigned b0, b1, b2, b3;
            ldm4(whaddr + (n * 32 + swb) * 16u, b0, b1, b2, b3);
            mma_bf16(acc[0], a0, a1, a2, a3, b0, b1);
            mma_bf16(acc[1], a0, a1, a2, a3, b2, b3);
        }

        const int g = L >> 2, q2 = (L & 3) * 2;
        float s = 0.0f;
#pragma unroll
        for (int nt = 0; nt < 2; nt++) {
            int n = nt * 8 + q2;
            float b0 = __ldg(&bh[n]), b1 = __ldg(&bh[n + 1]);
#pragma unroll
            for (int h = 0; h < 2; h++) {
                int m = w * 16 + g + 8 * h;
                const float* ar = action + (size_t)(r0 + m) * AA + n;
                float t0 = tanhf(acc[nt][2 * h + 0] + b0) - __ldg(&ar[0]);
                float t1 = tanhf(acc[nt][2 * h + 1] + b1) - __ldg(&ar[1]);
                s += t0 * t0 + t1 * t1;
            }
        }
        block_reduce_add_to(s, &g_sums[1]);
    }

    // ---- Fused finalize: last block writes the scalar ----
    if (tid == 0) {
        __threadfence();
        unsigned t = atomicAdd(&g_ticket, 1u);
        if (t == gridDim.x - 1) {
            double vq  = g_sums[0] / ((double)BB * (double)DD);
            double rec = g_sums[1] / ((double)BB * (double)AA);
            out[0] = (float)(rec + 1.25 * vq);
        }
    }
}

// ---------------------------------------------------------------------------
// Launch
// ---------------------------------------------------------------------------
extern "C" void kernel_launch(void* const* d_in, const int* in_sizes, int n_in,
                              void* d_out, int out_size) {
    const float* action = (const float*)d_in[0];
    const float* We1    = (const float*)d_in[1];
    const float* be1    = (const float*)d_in[2];
    const float* We2    = (const float*)d_in[3];
    const float* be2    = (const float*)d_in[4];
    const float* We3    = (const float*)d_in[5];
    const float* be3    = (const float*)d_in[6];
    const float* E      = (const float*)d_in[7];
    const float* Wd1    = (const float*)d_in[8];
    const float* bd1    = (const float*)d_in[9];
    const float* Wd2    = (const float*)d_in[10];
    const float* bd2    = (const float*)d_in[11];
    const float* Wh     = (const float*)d_in[12];
    const float* bh     = (const float*)d_in[13];
    float* out = (float*)d_out;

    cudaFuncSetAttribute((const void*)mega_kernel,
                         cudaFuncAttributeMaxDynamicSharedMemorySize, SMEM_TOTAL);

    prep_kernel<<<464, 256>>>((const float4*)We1, (const float4*)We2,
                              (const float4*)We3, (const float4*)Wd1,
                              (const float4*)Wd2, (const float4*)Wh,
                              (const float4*)E, E);
    mega_kernel<<<BB / 128, 256, SMEM_TOTAL>>>(action, be1, be2, be3, E,
                                               bd1, bd2, bh, out);
}

// round 13
// speedup vs baseline: 1.0780x; 1.0024x over previous
#include <cuda_runtime.h>
#include <cuda_bf16.h>
#include <cfloat>
#include <cstdint>

#define BB 32768
#define AA 16
#define HH 256
#define DD 128
#define KK 2048

// ---------------------------------------------------------------------------
// Globals: plain row-major bf16 weights/codebook (swizzle applied at cp.async)
// ---------------------------------------------------------------------------
__device__ __nv_bfloat16 g_We1b[HH * 64];    // [256][64], k>=16 zero (zero-init)
__device__ __nv_bfloat16 g_We2b[HH * HH];
__device__ __nv_bfloat16 g_We3b[DD * HH];
__device__ __nv_bfloat16 g_Wd1b[HH * DD];
__device__ __nv_bfloat16 g_Wd2b[HH * HH];
__device__ __nv_bfloat16 g_Whb[AA * HH];
__device__ __nv_bfloat16 g_Eb[KK * DD];
__device__ float    g_esq[KK];
__device__ double   g_sums[2];
__device__ unsigned g_ticket;

// smem (dynamic, 112KB per CTA -> 2 CTAs/SM, single wave of 256 blocks)
// Banks B0/B1/B2 (32KB each, 128 rows x 16 chunks ACH=16 layout) + W ring 16KB.
#define B0_OFF 0
#define B1_OFF 32768
#define B2_OFF 65536
#define WB_OFF 98304        // 2 x 8KB W chunks; dist: esq(8K)+red(2K)+bidx
#define SMEM_TOTAL 114688

// ---------------------------------------------------------------------------
__device__ __forceinline__ unsigned su(const void* p) {
    return (unsigned)__cvta_generic_to_shared(p);
}
__device__ __forceinline__ void cp16(unsigned dst, const void* src) {
    asm volatile("cp.async.cg.shared.global [%0], [%1], 16;\n" :: "r"(dst), "l"(src));
}
__device__ __forceinline__ void cpcommit() { asm volatile("cp.async.commit_group;\n"); }
template <int N>
__device__ __forceinline__ void cpwait() { asm volatile("cp.async.wait_group %0;\n" :: "n"(N)); }

__device__ __forceinline__ void ldm4(unsigned addr, unsigned& r0, unsigned& r1,
                                     unsigned& r2, unsigned& r3) {
    asm volatile("ldmatrix.sync.aligned.m8n8.x4.shared.b16 {%0,%1,%2,%3}, [%4];\n"
                 : "=r"(r0), "=r"(r1), "=r"(r2), "=r"(r3) : "r"(addr));
}
__device__ __forceinline__ void mma_bf16(float* c, unsigned a0, unsigned a1, unsigned a2,
                                         unsigned a3, unsigned b0, unsigned b1) {
    asm volatile(
        "mma.sync.aligned.m16n8k16.row.col.f32.bf16.bf16.f32 "
        "{%0,%1,%2,%3}, {%4,%5,%6,%7}, {%8,%9}, {%0,%1,%2,%3};\n"
        : "+f"(c[0]), "+f"(c[1]), "+f"(c[2]), "+f"(c[3])
        : "r"(a0), "r"(a1), "r"(a2), "r"(a3), "r"(b0), "r"(b1));
}
__device__ __forceinline__ unsigned pack_bf16(float a, float b) {
    __nv_bfloat162 h = __floats2bfloat162_rn(a, b);
    return *reinterpret_cast<unsigned*>(&h);
}

__device__ __forceinline__ void block_reduce_add_to(float v, double* target) {
    __shared__ float sbuf[8];
    int lane = threadIdx.x & 31, wid = threadIdx.x >> 5;
#pragma unroll
    for (int o = 16; o; o >>= 1) v += __shfl_xor_sync(0xffffffffu, v, o);
    if (lane == 0) sbuf[wid] = v;
    __syncthreads();
    if (wid == 0) {
        v = (lane < 8) ? sbuf[lane] : 0.0f;
#pragma unroll
        for (int o = 4; o; o >>= 1) v += __shfl_xor_sync(0xffffffffu, v, o);
        if (lane == 0) atomicAdd(target, (double)v);
    }
}

// ---------------------------------------------------------------------------
// prep: fp32 -> bf16 (plain layout), We1 padded to K=64, esq, zero sums/ticket
// ---------------------------------------------------------------------------
__global__ void prep_kernel(const float4* __restrict__ We1, const float4* __restrict__ We2,
                            const float4* __restrict__ We3, const float4* __restrict__ Wd1,
                            const float4* __restrict__ Wd2, const float4* __restrict__ Wh,
                            const float4* __restrict__ E, const float* __restrict__ Ef) {
    int blk = blockIdx.x;
    if (blk < 456) {
        int i = blk * 256 + threadIdx.x;
        const float4* src; uint2* dst; int j, dj;
        if (i < 16384)       { src = We2; dst = (uint2*)g_We2b; j = i;          dj = j; }
        else if (i < 24576)  { src = We3; dst = (uint2*)g_We3b; j = i - 16384;  dj = j; }
        else if (i < 32768)  { src = Wd1; dst = (uint2*)g_Wd1b; j = i - 24576;  dj = j; }
        else if (i < 49152)  { src = Wd2; dst = (uint2*)g_Wd2b; j = i - 32768;  dj = j; }
        else if (i < 114688) { src = E;   dst = (uint2*)g_Eb;   j = i - 49152;  dj = j; }
        else if (i < 115712) { src = We1; dst = (uint2*)g_We1b; j = i - 114688;
                               dj = (j >> 2) * 16 + (j & 3); }
        else                 { src = Wh;  dst = (uint2*)g_Whb;  j = i - 115712; dj = j; }
        float4 v = src[j];
        uint2 p;
        p.x = pack_bf16(v.x, v.y);
        p.y = pack_bf16(v.z, v.w);
        dst[dj] = p;
    } else {
        if (blk == 456 && threadIdx.x < 2) g_sums[threadIdx.x] = 0.0;
        if (blk == 456 && threadIdx.x == 2) g_ticket = 0u;
        int n = (blk - 456) * 256 + threadIdx.x;
        const float4* r = (const float4*)(Ef + (size_t)n * DD);
        float s = 0.0f;
#pragma unroll
        for (int i = 0; i < DD / 4; i++) {
            float4 v = r[i];
            float a = __bfloat162float(__float2bfloat16_rn(v.x));
            float b = __bfloat162float(__float2bfloat16_rn(v.y));
            float c = __bfloat162float(__float2bfloat16_rn(v.z));
            float d = __bfloat162float(__float2bfloat16_rn(v.w));
            s += a * a + b * b + c * c + d * d;
        }
        g_esq[n] = s;
    }
}

// ---------------------------------------------------------------------------
// W chunk issue: 128 rows x 32 k bf16 (8KB), swizzled (4 chunks/row, ^(row&3)).
// ---------------------------------------------------------------------------
__device__ __forceinline__ void wissue32(unsigned dstb, const __nv_bfloat16* Wg,
                                         int K, int kc, int tid) {
    int sn = tid >> 1;
    int cb = (tid & 1) * 2;
    const __nv_bfloat16* src = Wg + (size_t)sn * K + kc * 32;
#pragma unroll
    for (int i = 0; i < 2; i++) {
        int c = cb + i;
        cp16(dstb + (sn * 4 + (c ^ (sn & 3))) * 16u, src + c * 8);
    }
    cpcommit();
}

// ---------------------------------------------------------------------------
// GEMM stage (256 threads, M=128, BN=128): C = act(A[128xK] @ W[128xK]^T + b)
// A modes: 0 = single region ACH=8 (actB); 1 = single bank ACH=16 (K<=128);
//          2 = k-split across two ACH=16 banks (K=256).
// Output: one 32KB bank, 128 rows x 128 cols, ACH=16 (ng local 0..127).
// W streamed in 32-k chunks (8KB), double-buffered at wb.
// ---------------------------------------------------------------------------
template <int K, int AMODE>
__device__ __noinline__ void gemm_stage(
    unsigned Alo, unsigned Ahi,
    const __nv_bfloat16* __restrict__ Wg,
    const float* __restrict__ bias, int n0,
    char* __restrict__ Ob, bool relu, unsigned wb)
{
    constexpr int NCH = K / 32;
    const int tid = threadIdx.x;
    const int w = tid >> 5, L = tid & 31;
    const int wm = w & 3, wn = w >> 2;

    float acc[2][8][4];
#pragma unroll
    for (int a = 0; a < 2; a++)
#pragma unroll
        for (int b = 0; b < 8; b++)
#pragma unroll
            for (int c = 0; c < 4; c++) acc[a][b][c] = 0.0f;

    wissue32(wb, Wg, K, 0, tid);

    for (int kc = 0; kc < NCH; kc++) {
        if (kc + 1 < NCH) {
            wissue32(wb + ((kc + 1) & 1) * 8192u, Wg, K, kc + 1, tid);
            cpwait<1>();
        } else {
            cpwait<0>();
        }
        __syncthreads();

        unsigned Bb = wb + (kc & 1) * 8192u;
#pragma unroll
        for (int ks = 0; ks < 2; ks++) {
            unsigned a[2][4];
#pragma unroll
            for (int mt = 0; mt < 2; mt++) {
                int m  = wm * 32 + mt * 16 + (L & 15);
                int ck = kc * 4 + ks * 2 + (L >> 4);
                unsigned aaddr;
                if (AMODE == 0) {
                    aaddr = Alo + (m * 8 + (ck ^ (m & 7))) * 16u;
                } else if (AMODE == 1) {
                    aaddr = Alo + (m * 16 + ((ck & 8) | ((ck & 7) ^ (m & 7)))) * 16u;
                } else {
                    unsigned base = (ck < 16) ? Alo : Ahi;
                    int c2 = ck & 15;
                    aaddr = base + (m * 16 + ((c2 & 8) | ((c2 & 7) ^ (m & 7)))) * 16u;
                }
                ldm4(aaddr, a[mt][0], a[mt][1], a[mt][2], a[mt][3]);
            }
#pragma unroll
            for (int np = 0; np < 4; np++) {
                int n   = wn * 64 + np * 16 + (L & 7) + ((L >> 4) << 3);
                int ckb = ks * 2 + ((L >> 3) & 1);
                unsigned b0, b1, b2, b3;
                ldm4(Bb + (n * 4 + (ckb ^ (n & 3))) * 16u, b0, b1, b2, b3);
#pragma unroll
                for (int mt = 0; mt < 2; mt++) {
                    mma_bf16(acc[mt][np * 2 + 0], a[mt][0], a[mt][1], a[mt][2], a[mt][3], b0, b1);
                    mma_bf16(acc[mt][np * 2 + 1], a[mt][0], a[mt][1], a[mt][2], a[mt][3], b2, b3);
                }
            }
        }
        __syncthreads();   // also orders all A-reads before epilogue overwrite
    }

    const int g = L >> 2, q2 = (L & 3) * 2;
#pragma unroll
    for (int mt = 0; mt < 2; mt++) {
#pragma unroll
        for (int nt = 0; nt < 8; nt++) {
            int ng = wn * 64 + nt * 8 + q2;   // local col 0..127
            float b0 = __ldg(&bias[n0 + ng]), b1 = __ldg(&bias[n0 + ng + 1]);
            int c = ng >> 3;
#pragma unroll
            for (int h = 0; h < 2; h++) {
                int m = wm * 32 + mt * 16 + g + 8 * h;
                float v0 = acc[mt][nt][2 * h + 0] + b0;
                float v1 = acc[mt][nt][2 * h + 1] + b1;
                if (relu) { v0 = fmaxf(v0, 0.0f); v1 = fmaxf(v1, 0.0f); }
                int sw = (c & 8) | ((c & 7) ^ (m & 7));
                *reinterpret_cast<unsigned*>(Ob + (m * 16 + sw) * 16 + (ng & 7) * 2)
                    = pack_bf16(v0, v1);
            }
        }
    }
}

// ---------------------------------------------------------------------------
// Megakernel (256 threads, 128 rows/block, 2 CTAs/SM -> single wave)
// ---------------------------------------------------------------------------
__global__ __launch_bounds__(256, 2)
void mega_kernel(const float* __restrict__ action,
                 const float* __restrict__ be1, const float* __restrict__ be2,
                 const float* __restrict__ be3, const float* __restrict__ E,
                 const float* __restrict__ bd1, const float* __restrict__ bd2,
                 const float* __restrict__ bh, float* __restrict__ out) {
    extern __shared__ char sm[];
    const int tid = threadIdx.x;
    const int w = tid >> 5, L = tid & 31;
    const int wm = w & 3, wn = w >> 2;
    const int r0 = blockIdx.x * 128;

    char* B0p = sm + B0_OFF;
    char* B1p = sm + B1_OFF;
    char* B2p = sm + B2_OFF;
    unsigned b0a = su(B0p), b1a = su(B1p), b2a = su(B2p);
    unsigned wb  = su(sm + WB_OFF);
    float* esq_s = (float*)(sm + WB_OFF);
    float* red_v = (float*)(sm + WB_OFF + 8192);
    int*   red_i = (int*)  (sm + WB_OFF + 9216);
    int*   bidx  = (int*)  (sm + WB_OFF + 10240);

    // ---- Stage 1: pack action into B0 (ACH=8, K padded to 64); h1 -> B1|B2 ----
    {
        char* sActB = B0p;
        {
            int m = tid >> 1, hf = tid & 1;
            const float* ap = action + (size_t)(r0 + m) * AA + hf * 8;
            float4 f0 = __ldg((const float4*)ap);
            float4 f1 = __ldg((const float4*)(ap + 4));
            uint4 pk;
            pk.x = pack_bf16(f0.x, f0.y); pk.y = pack_bf16(f0.z, f0.w);
            pk.z = pack_bf16(f1.x, f1.y); pk.w = pack_bf16(f1.z, f1.w);
            *reinterpret_cast<uint4*>(sActB + (m * 8 + (hf ^ (m & 7))) * 16) = pk;
        }
        uint4 z = make_uint4(0, 0, 0, 0);
#pragma unroll
        for (int t = 0; t < 3; t++) {
            int idx = tid + t * 256;
            int m = idx / 6, c = 2 + idx % 6;
            *reinterpret_cast<uint4*>(sActB + (m * 8 + (c ^ (m & 7))) * 16) = z;
        }
        __syncthreads();
        gemm_stage<64, 0>(b0a, 0, g_We1b,            be1, 0,   B1p, true, wb);
        gemm_stage<64, 0>(b0a, 0, g_We1b + 128 * 64, be1, 128, B2p, true, wb);
    }
    __syncthreads();

    // ---- Stage 2: h2 = relu(h1 @ We2^T + be2): A=(B1,B2) -> out B0 | B1 ----
    gemm_stage<256, 2>(b1a, b2a, g_We2b,             be2, 0,   B0p, true, wb);
    gemm_stage<256, 2>(b1a, b2a, g_We2b + 128 * 256, be2, 128, B1p, true, wb);
    __syncthreads();

    // ---- Stage 3: enc = h2 @ We3^T + be3: A=(B0,B1) -> out B2 ----
    gemm_stage<256, 2>(b0a, b1a, g_We3b, be3, 0, B2p, false, wb);
    __syncthreads();

    // ---- Stage 4: dist + argmin over 2048 codes; enc=B2, E tiles in B0/B1 ----
    {
        unsigned eaddr = b2a;

        // group 0: esq (into WB) + E tile 0 (into B0)
#pragma unroll
        for (int t = 0; t < 2; t++) {
            int idx = tid + t * 256;
            cp16(su(esq_s) + idx * 16u, g_esq + idx * 4);
        }
#pragma unroll
        for (int t = 0; t < 8; t++) {
            int idx = tid + t * 256;
            int n = idx >> 4, c = idx & 15;
            int sw = (c & 8) | ((c & 7) ^ (n & 7));
            cp16(b0a + (n * 16 + sw) * 16u, (const char*)g_Eb + (size_t)n * 256 + c * 16);
        }
        cpcommit();

        float bestv[4];
        int   besti[4];
#pragma unroll
        for (int i = 0; i < 4; i++) { bestv[i] = FLT_MAX; besti[i] = 0; }

        for (int t0 = 0; t0 < 16; t0++) {
            if (t0 + 1 < 16) {
                unsigned bb = (t0 & 1) ? b0a : b1a;   // next tile's buffer
                const char* Eg = (const char*)g_Eb + (size_t)(t0 + 1) * 32768;
#pragma unroll
                for (int t = 0; t < 8; t++) {
                    int idx = tid + t * 256;
                    int n = idx >> 4, c = idx & 15;
                    int sw = (c & 8) | ((c & 7) ^ (n & 7));
                    cp16(bb + (n * 16 + sw) * 16u, Eg + (size_t)n * 256 + c * 16);
                }
                cpcommit();
                cpwait<1>();
            } else {
                cpwait<0>();
            }
            __syncthreads();

            unsigned Bb = (t0 & 1) ? b1a : b0a;
            float acc[2][8][4];
#pragma unroll
            for (int a = 0; a < 2; a++)
#pragma unroll
                for (int b = 0; b < 8; b++)
#pragma unroll
                    for (int c = 0; c < 4; c++) acc[a][b][c] = 0.0f;

#pragma unroll
            for (int ks = 0; ks < 8; ks++) {
                unsigned a[2][4];
#pragma unroll
                for (int mt = 0; mt < 2; mt++) {
                    int m  = wm * 32 + mt * 16 + (L & 15);
                    int ck = ks * 2 + (L >> 4);
                    int sw = (ck & 8) | ((ck & 7) ^ (m & 7));
                    ldm4(eaddr + (m * 16 + sw) * 16u, a[mt][0], a[mt][1], a[mt][2], a[mt][3]);
                }
#pragma unroll
                for (int np = 0; np < 4; np++) {
                    int n   = wn * 64 + np * 16 + (L & 7) + ((L >> 4) << 3);
                    int ckb = ks * 2 + ((L >> 3) & 1);
                    int sw  = (ckb & 8) | ((ckb & 7) ^ (n & 7));
                    unsigned b0, b1, b2, b3;
                    ldm4(Bb + (n * 16 + sw) * 16u, b0, b1, b2, b3);
#pragma unroll
                    for (int mt = 0; mt < 2; mt++) {
                        mma_bf16(acc[mt][np * 2 + 0], a[mt][0], a[mt][1], a[mt][2], a[mt][3], b0, b1);
                        mma_bf16(acc[mt][np * 2 + 1], a[mt][0], a[mt][1], a[mt][2], a[mt][3], b2, b3);
                    }
                }
            }

            const int q2 = (L & 3) * 2;
#pragma unroll
            for (int nt = 0; nt < 8; nt++) {
                int n = t0 * 128 + wn * 64 + nt * 8 + q2;
                float es0 = esq_s[n];
                float es1 = esq_s[n + 1];
#pragma unroll
                for (int mt = 0; mt < 2; mt++) {
#pragma unroll
                    for (int h = 0; h < 2; h++) {
                        int r = mt * 2 + h;
                        float v0 = fmaf(-2.0f, acc[mt][nt][2 * h + 0], es0);
                        float v1 = fmaf(-2.0f, acc[mt][nt][2 * h + 1], es1);
                        if (v0 < bestv[r]) { bestv[r] = v0; besti[r] = n; }
                        if (v1 < bestv[r]) { bestv[r] = v1; besti[r] = n + 1; }
                    }
                }
            }
            __syncthreads();
        }

#pragma unroll
        for (int r = 0; r < 4; r++) {
            float v = bestv[r];
            int   ii = besti[r];
#pragma unroll
            for (int o = 1; o <= 2; o <<= 1) {
                float v2 = __shfl_xor_sync(0xffffffffu, v, o);
                int   i2 = __shfl_xor_sync(0xffffffffu, ii, o);
                if (v2 < v || (v2 == v && i2 < ii)) { v = v2; ii = i2; }
            }
            bestv[r] = v; besti[r] = ii;
        }
        if ((L & 3) == 0) {
            int g = L >> 2;
#pragma unroll
            for (int r = 0; r < 4; r++) {
                int mt = r >> 1, h = r & 1;
                int row = wm * 32 + mt * 16 + g + 8 * h;
                red_v[row * 2 + wn] = bestv[r];
                red_i[row * 2 + wn] = besti[r];
            }
        }
        __syncthreads();
        if (tid < 128) {
            float v0 = red_v[tid * 2], v1 = red_v[tid * 2 + 1];
            int   i0 = red_i[tid * 2], i1 = red_i[tid * 2 + 1];
            bidx[tid] = (v1 < v0 || (v1 == v0 && i1 < i0)) ? i1 : i0;
        }
        __syncthreads();
    }

    // ---- Stage 5: gather q = E[idx] -> B0 (swizzled), vq loss (enc in B2) ----
    {
        int m = tid >> 1, hf = tid & 1;
        int code = bidx[m];
        const float4* Ep = reinterpret_cast<const float4*>(E + ((size_t)code << 7) + hf * 64);
        float s = 0.0f;
#pragma unroll
        for (int j = 0; j < 8; j++) {
            int c = hf * 8 + j;
            float4 q0 = __ldg(&Ep[2 * j]);
            float4 q1 = __ldg(&Ep[2 * j + 1]);
            int sw = (c & 8) | ((c & 7) ^ (m & 7));
            uint4 ev = *reinterpret_cast<uint4*>(B2p + (m * 16 + sw) * 16);
            const __nv_bfloat162* eh = reinterpret_cast<const __nv_bfloat162*>(&ev);
            float2 e0 = __bfloat1622float2(eh[0]);
            float2 e1 = __bfloat1622float2(eh[1]);
            float2 e2 = __bfloat1622float2(eh[2]);
            float2 e3 = __bfloat1622float2(eh[3]);
            float d;
            d = e0.x - q0.x; s += d * d;  d = e0.y - q0.y; s += d * d;
            d = e1.x - q0.z; s += d * d;  d = e1.y - q0.w; s += d * d;
            d = e2.x - q1.x; s += d * d;  d = e2.y - q1.y; s += d * d;
            d = e3.x - q1.z; s += d * d;  d = e3.y - q1.w; s += d * d;
            uint4 pk;
            pk.x = pack_bf16(q0.x, q0.y); pk.y = pack_bf16(q0.z, q0.w);
            pk.z = pack_bf16(q1.x, q1.y); pk.w = pack_bf16(q1.z, q1.w);
            *reinterpret_cast<uint4*>(B0p + (m * 16 + sw) * 16) = pk;
        }
        block_reduce_add_to(s, &g_sums[0]);
    }
    __syncthreads();

    // ---- Stage 6: d1 = relu(q @ Wd1^T + bd1): A=B0 -> out B1 | B2 ----
    gemm_stage<128, 1>(b0a, 0, g_Wd1b,             bd1, 0,   B1p, true, wb);
    gemm_stage<128, 1>(b0a, 0, g_Wd1b + 128 * 128, bd1, 128, B2p, true, wb);
    __syncthreads();

    // ---- Stage 7: d2 = relu(d1 @ Wd2^T + bd2): A=(B1,B2) -> out B0 | B1 ----
    gemm_stage<256, 2>(b1a, b2a, g_Wd2b,             bd2, 0,   B0p, true, wb);
    gemm_stage<256, 2>(b1a, b2a, g_Wd2b + 128 * 256, bd2, 128, B1p, true, wb);
    __syncthreads();

    // ---- Stage 8: head = tanh(d2 @ Wh^T + bh), recons loss; A=(B0,B1) ----
    {
        unsigned whaddr = wb;   // 16 x 256 bf16 swizzled (8KB) in W region
#pragma unroll
        for (int i = 0; i < 2; i++) {
            int idx = tid * 2 + i;
            int n = idx >> 5, c = idx & 31;
            int sw = (c & 24) | ((c & 7) ^ (n & 7));
            cp16(whaddr + (n * 32 + sw) * 16u, g_Whb + (size_t)n * HH + c * 8);
        }
        cpcommit(); cpwait<0>();
        __syncthreads();

        float acc[2][4];
#pragma unroll
        for (int a = 0; a < 2; a++)
#pragma unroll
            for (int c = 0; c < 4; c++) acc[a][c] = 0.0f;

#pragma unroll
        for (int ks = 0; ks < 16; ks++) {
            int m  = w * 16 + (L & 15);
            int ck = ks * 2 + (L >> 4);
            unsigned base = (ck < 16) ? b0a : b1a;
            int c2 = ck & 15;
            int sw = (c2 & 8) | ((c2 & 7) ^ (m & 7));
            unsigned a0, a1, a2, a3;
            ldm4(base + (m * 16 + sw) * 16u, a0, a1, a2, a3);
            int n   = (L & 7) + ((L >> 4) << 3);
            int ckb = ks * 2 + ((L >> 3) & 1);
            int swb = (ckb & 24) | ((ckb & 7) ^ (n & 7));
            unsigned b0, b1, b2, b3;
            ldm4(whaddr + (n * 32 + swb) * 16u, b0, b1, b2, b3);
            mma_bf16(acc[0], a0, a1, a2, a3, b0, b1);
            mma_bf16(acc[1], a0, a1, a2, a3, b2, b3);
        }

        const int g = L >> 2, q2 = (L & 3) * 2;
        float s = 0.0f;
#pragma unroll
        for (int nt = 0; nt < 2; nt++) {
            int n = nt * 8 + q2;
            float b0 = __ldg(&bh[n]), b1 = __ldg(&bh[n + 1]);
#pragma unroll
            for (int h = 0; h < 2; h++) {
                int m = w * 16 + g + 8 * h;
                const float* ar = action + (size_t)(r0 + m) * AA + n;
                float t0 = tanhf(acc[nt][2 * h + 0] + b0) - __ldg(&ar[0]);
                float t1 = tanhf(acc[nt][2 * h + 1] + b1) - __ldg(&ar[1]);
                s += t0 * t0 + t1 * t1;
            }
        }
        block_reduce_add_to(s, &g_sums[1]);
    }

    // ---- fused finalize ----
    if (tid == 0) {
        __threadfence();
        unsigned t = atomicAdd(&g_ticket, 1u);
        if (t == gridDim.x - 1) {
            double vq  = g_sums[0] / ((double)BB * (double)DD);
            double rec = g_sums[1] / ((double)BB * (double)AA);
            out[0] = (float)(rec + 1.25 * vq);
        }
    }
}

// ---------------------------------------------------------------------------
extern "C" void kernel_launch(void* const* d_in, const int* in_sizes, int n_in,
                              void* d_out, int out_size) {
    const float* action = (const float*)d_in[0];
    const float* We1    = (const float*)d_in[1];
    const float* be1    = (const float*)d_in[2];
    const float* We2    = (const float*)d_in[3];
    const float* be2    = (const float*)d_in[4];
    const float* We3    = (const float*)d_in[5];
    const float* be3    = (const float*)d_in[6];
    const float* E      = (const float*)d_in[7];
    const float* Wd1    = (const float*)d_in[8];
    const float* bd1    = (const float*)d_in[9];
    const float* Wd2    = (const float*)d_in[10];
    const float* bd2    = (const float*)d_in[11];
    const float* Wh     = (const float*)d_in[12];
    const float* bh     = (const float*)d_in[13];
    float* out = (float*)d_out;

    cudaFuncSetAttribute((const void*)mega_kernel,
                         cudaFuncAttributeMaxDynamicSharedMemorySize, SMEM_TOTAL);

    prep_kernel<<<464, 256>>>((const float4*)We1, (const float4*)We2,
                              (const float4*)We3, (const float4*)Wd1,
                              (const float4*)Wd2, (const float4*)Wh,
                              (const float4*)E, E);
    mega_kernel<<<BB / 128, 256, SMEM_TOTAL>>>(action, be1, be2, be3, E,
                                               bd1, bd2, bh, out);
}

// round 14
// speedup vs baseline: 1.1492x; 1.0660x over previous
#include <cuda_runtime.h>
#include <cuda_bf16.h>
#include <cfloat>
#include <cstdint>

#define BB 32768
#define AA 16
#define HH 256
#define DD 128
#define KK 2048

// ---------------------------------------------------------------------------
// Globals: plain row-major bf16 weights/codebook (swizzle applied at cp.async)
// ---------------------------------------------------------------------------
__device__ __nv_bfloat16 g_We1b[HH * 64];    // [256][64], k>=16 zero (zero-init)
__device__ __nv_bfloat16 g_We2b[HH * HH];
__device__ __nv_bfloat16 g_We3b[DD * HH];
__device__ __nv_bfloat16 g_Wd1b[HH * DD];
__device__ __nv_bfloat16 g_Wd2b[HH * HH];
__device__ __nv_bfloat16 g_Whb[AA * HH];
__device__ __nv_bfloat16 g_Eb[KK * DD];
__device__ float    g_esq[KK];
__device__ double   g_sums[2];
__device__ unsigned g_ticket;

// smem (dynamic, 112KB per CTA -> 2 CTAs/SM, single wave of 256 blocks)
// Banks B0/B1/B2 (32KB each, 128 rows x 16 chunks ACH=16 layout) + W ring 16KB.
#define B0_OFF 0
#define B1_OFF 32768
#define B2_OFF 65536
#define WB_OFF 98304        // 2 x 8KB W chunks; dist: esq(8K)+red(2K)+bidx
#define SMEM_TOTAL 114688

// ---------------------------------------------------------------------------
__device__ __forceinline__ unsigned su(const void* p) {
    return (unsigned)__cvta_generic_to_shared(p);
}
__device__ __forceinline__ void cp16(unsigned dst, const void* src) {
    asm volatile("cp.async.cg.shared.global [%0], [%1], 16;\n" :: "r"(dst), "l"(src));
}
__device__ __forceinline__ void cpcommit() { asm volatile("cp.async.commit_group;\n"); }
template <int N>
__device__ __forceinline__ void cpwait() { asm volatile("cp.async.wait_group %0;\n" :: "n"(N)); }

__device__ __forceinline__ void ldm4(unsigned addr, unsigned& r0, unsigned& r1,
                                     unsigned& r2, unsigned& r3) {
    asm volatile("ldmatrix.sync.aligned.m8n8.x4.shared.b16 {%0,%1,%2,%3}, [%4];\n"
                 : "=r"(r0), "=r"(r1), "=r"(r2), "=r"(r3) : "r"(addr));
}
__device__ __forceinline__ void mma_bf16(float* c, unsigned a0, unsigned a1, unsigned a2,
                                         unsigned a3, unsigned b0, unsigned b1) {
    asm volatile(
        "mma.sync.aligned.m16n8k16.row.col.f32.bf16.bf16.f32 "
        "{%0,%1,%2,%3}, {%4,%5,%6,%7}, {%8,%9}, {%0,%1,%2,%3};\n"
        : "+f"(c[0]), "+f"(c[1]), "+f"(c[2]), "+f"(c[3])
        : "r"(a0), "r"(a1), "r"(a2), "r"(a3), "r"(b0), "r"(b1));
}
__device__ __forceinline__ unsigned pack_bf16(float a, float b) {
    __nv_bfloat162 h = __floats2bfloat162_rn(a, b);
    return *reinterpret_cast<unsigned*>(&h);
}

__device__ __forceinline__ void block_reduce_add_to(float v, double* target) {
    __shared__ float sbuf[8];
    int lane = threadIdx.x & 31, wid = threadIdx.x >> 5;
#pragma unroll
    for (int o = 16; o; o >>= 1) v += __shfl_xor_sync(0xffffffffu, v, o);
    if (lane == 0) sbuf[wid] = v;
    __syncthreads();
    if (wid == 0) {
        v = (lane < 8) ? sbuf[lane] : 0.0f;
#pragma unroll
        for (int o = 4; o; o >>= 1) v += __shfl_xor_sync(0xffffffffu, v, o);
        if (lane == 0) atomicAdd(target, (double)v);
    }
}

// ---------------------------------------------------------------------------
// prep: fp32 -> bf16 (plain layout), We1 padded to K=64, esq, zero sums/ticket
// ---------------------------------------------------------------------------
__global__ void prep_kernel(const float4* __restrict__ We1, const float4* __restrict__ We2,
                            const float4* __restrict__ We3, const float4* __restrict__ Wd1,
                            const float4* __restrict__ Wd2, const float4* __restrict__ Wh,
                            const float4* __restrict__ E, const float* __restrict__ Ef) {
    int blk = blockIdx.x;
    if (blk < 456) {
        int i = blk * 256 + threadIdx.x;
        const float4* src; uint2* dst; int j, dj;
        if (i < 16384)       { src = We2; dst = (uint2*)g_We2b; j = i;          dj = j; }
        else if (i < 24576)  { src = We3; dst = (uint2*)g_We3b; j = i - 16384;  dj = j; }
        else if (i < 32768)  { src = Wd1; dst = (uint2*)g_Wd1b; j = i - 24576;  dj = j; }
        else if (i < 49152)  { src = Wd2; dst = (uint2*)g_Wd2b; j = i - 32768;  dj = j; }
        else if (i < 114688) { src = E;   dst = (uint2*)g_Eb;   j = i - 49152;  dj = j; }
        else if (i < 115712) { src = We1; dst = (uint2*)g_We1b; j = i - 114688;
                               dj = (j >> 2) * 16 + (j & 3); }
        else                 { src = Wh;  dst = (uint2*)g_Whb;  j = i - 115712; dj = j; }
        float4 v = src[j];
        uint2 p;
        p.x = pack_bf16(v.x, v.y);
        p.y = pack_bf16(v.z, v.w);
        dst[dj] = p;
    } else {
        if (blk == 456 && threadIdx.x < 2) g_sums[threadIdx.x] = 0.0;
        if (blk == 456 && threadIdx.x == 2) g_ticket = 0u;
        int n = (blk - 456) * 256 + threadIdx.x;
        const float4* r = (const float4*)(Ef + (size_t)n * DD);
        float s = 0.0f;
#pragma unroll
        for (int i = 0; i < DD / 4; i++) {
            float4 v = r[i];
            float a = __bfloat162float(__float2bfloat16_rn(v.x));
            float b = __bfloat162float(__float2bfloat16_rn(v.y));
            float c = __bfloat162float(__float2bfloat16_rn(v.z));
            float d = __bfloat162float(__float2bfloat16_rn(v.w));
            s += a * a + b * b + c * c + d * d;
        }
        g_esq[n] = s;
    }
}

// ---------------------------------------------------------------------------
// W chunk issue: 128 rows x 32 k bf16 (8KB). Conflict-free swizzle:
// chunk c placed at c ^ ((row>>1)&3)  — distinct banks across 8-row phases.
// ---------------------------------------------------------------------------
__device__ __forceinline__ void wissue32(unsigned dstb, const __nv_bfloat16* Wg,
                                         int K, int kc, int tid) {
    int sn = tid >> 1;
    int cb = (tid & 1) * 2;
    const __nv_bfloat16* src = Wg + (size_t)sn * K + kc * 32;
#pragma unroll
    for (int i = 0; i < 2; i++) {
        int c = cb + i;
        cp16(dstb + (sn * 4 + (c ^ ((sn >> 1) & 3))) * 16u, src + c * 8);
    }
    cpcommit();
}

// ---------------------------------------------------------------------------
// GEMM stage (256 threads, M=128, BN=128): C = act(A[128xK] @ W[128xK]^T + b)
// A modes: 0 = single region ACH=8 (actB); 1 = single bank ACH=16 (K<=128);
//          2 = k-split across two ACH=16 banks (K=256).
// Output: one 32KB bank, 128 rows x 128 cols, ACH=16 (ng local 0..127).
// W streamed in 32-k chunks (8KB), double-buffered at wb, conflict-free.
// ---------------------------------------------------------------------------
template <int K, int AMODE>
__device__ __noinline__ void gemm_stage(
    unsigned Alo, unsigned Ahi,
    const __nv_bfloat16* __restrict__ Wg,
    const float* __restrict__ bias, int n0,
    char* __restrict__ Ob, bool relu, unsigned wb)
{
    constexpr int NCH = K / 32;
    const int tid = threadIdx.x;
    const int w = tid >> 5, L = tid & 31;
    const int wm = w & 3, wn = w >> 2;

    float acc[2][8][4];
#pragma unroll
    for (int a = 0; a < 2; a++)
#pragma unroll
        for (int b = 0; b < 8; b++)
#pragma unroll
            for (int c = 0; c < 4; c++) acc[a][b][c] = 0.0f;

    wissue32(wb, Wg, K, 0, tid);

    for (int kc = 0; kc < NCH; kc++) {
        if (kc + 1 < NCH) {
            wissue32(wb + ((kc + 1) & 1) * 8192u, Wg, K, kc + 1, tid);
            cpwait<1>();
        } else {
            cpwait<0>();
        }
        __syncthreads();

        unsigned Bb = wb + (kc & 1) * 8192u;
#pragma unroll
        for (int ks = 0; ks < 2; ks++) {
            unsigned a[2][4];
#pragma unroll
            for (int mt = 0; mt < 2; mt++) {
                int m  = wm * 32 + mt * 16 + (L & 15);
                int ck = kc * 4 + ks * 2 + (L >> 4);
                unsigned aaddr;
                if (AMODE == 0) {
                    aaddr = Alo + (m * 8 + (ck ^ (m & 7))) * 16u;
                } else if (AMODE == 1) {
                    aaddr = Alo + (m * 16 + ((ck & 8) | ((ck & 7) ^ (m & 7)))) * 16u;
                } else {
                    unsigned base = (ck < 16) ? Alo : Ahi;
                    int c2 = ck & 15;
                    aaddr = base + (m * 16 + ((c2 & 8) | ((c2 & 7) ^ (m & 7)))) * 16u;
                }
                ldm4(aaddr, a[mt][0], a[mt][1], a[mt][2], a[mt][3]);
            }
#pragma unroll
            for (int np = 0; np < 4; np++) {
                int n   = wn * 64 + np * 16 + (L & 7) + ((L >> 4) << 3);
                int ckb = ks * 2 + ((L >> 3) & 1);
                unsigned b0, b1, b2, b3;
                ldm4(Bb + (n * 4 + (ckb ^ ((n >> 1) & 3))) * 16u, b0, b1, b2, b3);
#pragma unroll
                for (int mt = 0; mt < 2; mt++) {
                    mma_bf16(acc[mt][np * 2 + 0], a[mt][0], a[mt][1], a[mt][2], a[mt][3], b0, b1);
                    mma_bf16(acc[mt][np * 2 + 1], a[mt][0], a[mt][1], a[mt][2], a[mt][3], b2, b3);
                }
            }
        }
        __syncthreads();   // also orders all A-reads before epilogue overwrite
    }

    const int g = L >> 2, q2 = (L & 3) * 2;
#pragma unroll
    for (int mt = 0; mt < 2; mt++) {
#pragma unroll
        for (int nt = 0; nt < 8; nt++) {
            int ng = wn * 64 + nt * 8 + q2;   // local col 0..127
            float b0 = __ldg(&bias[n0 + ng]), b1 = __ldg(&bias[n0 + ng + 1]);
            int c = ng >> 3;
#pragma unroll
            for (int h = 0; h < 2; h++) {
                int m = wm * 32 + mt * 16 + g + 8 * h;
                float v0 = acc[mt][nt][2 * h + 0] + b0;
                float v1 = acc[mt][nt][2 * h + 1] + b1;
                if (relu) { v0 = fmaxf(v0, 0.0f); v1 = fmaxf(v1, 0.0f); }
                int sw = (c & 8) | ((c & 7) ^ (m & 7));
                *reinterpret_cast<unsigned*>(Ob + (m * 16 + sw) * 16 + (ng & 7) * 2)
                    = pack_bf16(v0, v1);
            }
        }
    }
}

// ---------------------------------------------------------------------------
// Megakernel (256 threads, 128 rows/block, 2 CTAs/SM -> single wave)
// ---------------------------------------------------------------------------
__global__ __launch_bounds__(256, 2)
void mega_kernel(const float* __restrict__ action,
                 const float* __restrict__ be1, const float* __restrict__ be2,
                 const float* __restrict__ be3, const float* __restrict__ E,
                 const float* __restrict__ bd1, const float* __restrict__ bd2,
                 const float* __restrict__ bh, float* __restrict__ out) {
    extern __shared__ char sm[];
    const int tid = threadIdx.x;
    const int w = tid >> 5, L = tid & 31;
    const int wm = w & 3, wn = w >> 2;
    const int r0 = blockIdx.x * 128;

    char* B0p = sm + B0_OFF;
    char* B1p = sm + B1_OFF;
    char* B2p = sm + B2_OFF;
    unsigned b0a = su(B0p), b1a = su(B1p), b2a = su(B2p);
    unsigned wb  = su(sm + WB_OFF);
    float* esq_s = (float*)(sm + WB_OFF);
    float* red_v = (float*)(sm + WB_OFF + 8192);
    int*   red_i = (int*)  (sm + WB_OFF + 9216);
    int*   bidx  = (int*)  (sm + WB_OFF + 10240);

    // ---- Stage 1: pack action into B0 (ACH=8, K padded to 64); h1 -> B1|B2 ----
    {
        char* sActB = B0p;
        {
            int m = tid >> 1, hf = tid & 1;
            const float* ap = action + (size_t)(r0 + m) * AA + hf * 8;
            float4 f0 = __ldg((const float4*)ap);
            float4 f1 = __ldg((const float4*)(ap + 4));
            uint4 pk;
            pk.x = pack_bf16(f0.x, f0.y); pk.y = pack_bf16(f0.z, f0.w);
            pk.z = pack_bf16(f1.x, f1.y); pk.w = pack_bf16(f1.z, f1.w);
            *reinterpret_cast<uint4*>(sActB + (m * 8 + (hf ^ (m & 7))) * 16) = pk;
        }
        uint4 z = make_uint4(0, 0, 0, 0);
#pragma unroll
        for (int t = 0; t < 3; t++) {
            int idx = tid + t * 256;
            int m = idx / 6, c = 2 + idx % 6;
            *reinterpret_cast<uint4*>(sActB + (m * 8 + (c ^ (m & 7))) * 16) = z;
        }
        __syncthreads();
        gemm_stage<64, 0>(b0a, 0, g_We1b,            be1, 0,   B1p, true, wb);
        gemm_stage<64, 0>(b0a, 0, g_We1b + 128 * 64, be1, 128, B2p, true, wb);
    }
    __syncthreads();

    // ---- Stage 2: h2 = relu(h1 @ We2^T + be2): A=(B1,B2) -> out B0 | B1 ----
    gemm_stage<256, 2>(b1a, b2a, g_We2b,             be2, 0,   B0p, true, wb);
    gemm_stage<256, 2>(b1a, b2a, g_We2b + 128 * 256, be2, 128, B1p, true, wb);
    __syncthreads();

    // ---- Stage 3: enc = h2 @ We3^T + be3: A=(B0,B1) -> out B2 ----
    gemm_stage<256, 2>(b0a, b1a, g_We3b, be3, 0, B2p, false, wb);
    __syncthreads();

    // ---- Stage 4: dist + argmin over 2048 codes; enc=B2, E tiles in B0/B1 ----
    {
        unsigned eaddr = b2a;

        // group 0: esq (into WB) + E tile 0 (into B0)
#pragma unroll
        for (int t = 0; t < 2; t++) {
            int idx = tid + t * 256;
            cp16(su(esq_s) + idx * 16u, g_esq + idx * 4);
        }
#pragma unroll
        for (int t = 0; t < 8; t++) {
            int idx = tid + t * 256;
            int n = idx >> 4, c = idx & 15;
            int sw = (c & 8) | ((c & 7) ^ (n & 7));
            cp16(b0a + (n * 16 + sw) * 16u, (const char*)g_Eb + (size_t)n * 256 + c * 16);
        }
        cpcommit();

        float bestv[4];
        int   besti[4];
#pragma unroll
        for (int i = 0; i < 4; i++) { bestv[i] = FLT_MAX; besti[i] = 0; }

        for (int t0 = 0; t0 < 16; t0++) {
            if (t0 + 1 < 16) {
                unsigned bb = (t0 & 1) ? b0a : b1a;   // next tile's buffer
                const char* Eg = (const char*)g_Eb + (size_t)(t0 + 1) * 32768;
#pragma unroll
                for (int t = 0; t < 8; t++) {
                    int idx = tid + t * 256;
                    int n = idx >> 4, c = idx & 15;
                    int sw = (c & 8) | ((c & 7) ^ (n & 7));
                    cp16(bb + (n * 16 + sw) * 16u, Eg + (size_t)n * 256 + c * 16);
                }
                cpcommit();
                cpwait<1>();
            } else {
                cpwait<0>();
            }
            __syncthreads();

            unsigned Bb = (t0 & 1) ? b1a : b0a;
            float acc[2][8][4];
#pragma unroll
            for (int a = 0; a < 2; a++)
#pragma unroll
                for (int b = 0; b < 8; b++)
#pragma unroll
                    for (int c = 0; c < 4; c++) acc[a][b][c] = 0.0f;

#pragma unroll
            for (int ks = 0; ks < 8; ks++) {
                unsigned a[2][4];
#pragma unroll
                for (int mt = 0; mt < 2; mt++) {
                    int m  = wm * 32 + mt * 16 + (L & 15);
                    int ck = ks * 2 + (L >> 4);
                    int sw = (ck & 8) | ((ck & 7) ^ (m & 7));
                    ldm4(eaddr + (m * 16 + sw) * 16u, a[mt][0], a[mt][1], a[mt][2], a[mt][3]);
                }
#pragma unroll
                for (int np = 0; np < 4; np++) {
                    int n   = wn * 64 + np * 16 + (L & 7) + ((L >> 4) << 3);
                    int ckb = ks * 2 + ((L >> 3) & 1);
                    int sw  = (ckb & 8) | ((ckb & 7) ^ (n & 7));
                    unsigned b0, b1, b2, b3;
                    ldm4(Bb + (n * 16 + sw) * 16u, b0, b1, b2, b3);
#pragma unroll
                    for (int mt = 0; mt < 2; mt++) {
                        mma_bf16(acc[mt][np * 2 + 0], a[mt][0], a[mt][1], a[mt][2], a[mt][3], b0, b1);
                        mma_bf16(acc[mt][np * 2 + 1], a[mt][0], a[mt][1], a[mt][2], a[mt][3], b2, b3);
                    }
                }
            }

            const int q2 = (L & 3) * 2;
#pragma unroll
            for (int nt = 0; nt < 8; nt++) {
                int n = t0 * 128 + wn * 64 + nt * 8 + q2;
                float es0 = esq_s[n];
                float es1 = esq_s[n + 1];
#pragma unroll
                for (int mt = 0; mt < 2; mt++) {
#pragma unroll
                    for (int h = 0; h < 2; h++) {
                        int r = mt * 2 + h;
                        float v0 = fmaf(-2.0f, acc[mt][nt][2 * h + 0], es0);
                        float v1 = fmaf(-2.0f, acc[mt][nt][2 * h + 1], es1);
                        if (v0 < bestv[r]) { bestv[r] = v0; besti[r] = n; }
                        if (v1 < bestv[r]) { bestv[r] = v1; besti[r] = n + 1; }
                    }
                }
            }
            __syncthreads();
        }

#pragma unroll
        for (int r = 0; r < 4; r++) {
            float v = bestv[r];
            int   ii = besti[r];
#pragma unroll
            for (int o = 1; o <= 2; o <<= 1) {
                float v2 = __shfl_xor_sync(0xffffffffu, v, o);
                int   i2 = __shfl_xor_sync(0xffffffffu, ii, o);
                if (v2 < v || (v2 == v && i2 < ii)) { v = v2; ii = i2; }
            }
            bestv[r] = v; besti[r] = ii;
        }
        if ((L & 3) == 0) {
            int g = L >> 2;
#pragma unroll
            for (int r = 0; r < 4; r++) {
                int mt = r >> 1, h = r & 1;
                int row = wm * 32 + mt * 16 + g + 8 * h;
                red_v[row * 2 + wn] = bestv[r];
                red_i[row * 2 + wn] = besti[r];
            }
        }
        __syncthreads();
        if (tid < 128) {
            float v0 = red_v[tid * 2], v1 = red_v[tid * 2 + 1];
            int   i0 = red_i[tid * 2], i1 = red_i[tid * 2 + 1];
            bidx[tid] = (v1 < v0 || (v1 == v0 && i1 < i0)) ? i1 : i0;
        }
        __syncthreads();
    }

    // ---- Stage 5: gather q = E[idx] -> B0 (swizzled), vq loss (enc in B2) ----
    {
        int m = tid >> 1, hf = tid & 1;
        int code = bidx[m];
        const float4* Ep = reinterpret_cast<const float4*>(E + ((size_t)code << 7) + hf * 64);
        float s = 0.0f;
#pragma unroll
        for (int j = 0; j < 8; j++) {
            int c = hf * 8 + j;
            float4 q0 = __ldg(&Ep[2 * j]);
            float4 q1 = __ldg(&Ep[2 * j + 1]);
            int sw = (c & 8) | ((c & 7) ^ (m & 7));
            uint4 ev = *reinterpret_cast<uint4*>(B2p + (m * 16 + sw) * 16);
            const __nv_bfloat162* eh = reinterpret_cast<const __nv_bfloat162*>(&ev);
            float2 e0 = __bfloat1622float2(eh[0]);
            float2 e1 = __bfloat1622float2(eh[1]);
            float2 e2 = __bfloat1622float2(eh[2]);
            float2 e3 = __bfloat1622float2(eh[3]);
            float d;
            d = e0.x - q0.x; s += d * d;  d = e0.y - q0.y; s += d * d;
            d = e1.x - q0.z; s += d * d;  d = e1.y - q0.w; s += d * d;
            d = e2.x - q1.x; s += d * d;  d = e2.y - q1.y; s += d * d;
            d = e3.x - q1.z; s += d * d;  d = e3.y - q1.w; s += d * d;
            uint4 pk;
            pk.x = pack_bf16(q0.x, q0.y); pk.y = pack_bf16(q0.z, q0.w);
            pk.z = pack_bf16(q1.x, q1.y); pk.w = pack_bf16(q1.z, q1.w);
            *reinterpret_cast<uint4*>(B0p + (m * 16 + sw) * 16) = pk;
        }
        block_reduce_add_to(s, &g_sums[0]);
    }
    __syncthreads();

    // ---- Stage 6: d1 = relu(q @ Wd1^T + bd1): A=B0 -> out B1 | B2 ----
    gemm_stage<128, 1>(b0a, 0, g_Wd1b,             bd1, 0,   B1p, true, wb);
    gemm_stage<128, 1>(b0a, 0, g_Wd1b + 128 * 128, bd1, 128, B2p, true, wb);
    __syncthreads();

    // ---- Stage 7: d2 = relu(d1 @ Wd2^T + bd2): A=(B1,B2) -> out B0 | B1 ----
    gemm_stage<256, 2>(b1a, b2a, g_Wd2b,             bd2, 0,   B0p, true, wb);
    gemm_stage<256, 2>(b1a, b2a, g_Wd2b + 128 * 256, bd2, 128, B1p, true, wb);
    __syncthreads();

    // ---- Stage 8: head = tanh(d2 @ Wh^T + bh), recons loss; A=(B0,B1) ----
    {
        unsigned whaddr = wb;   // 16 x 256 bf16 swizzled (8KB) in W region
#pragma unroll
        for (int i = 0; i < 2; i++) {
            int idx = tid * 2 + i;
            int n = idx >> 5, c = idx & 31;
            int sw = (c & 24) | ((c & 7) ^ (n & 7));
            cp16(whaddr + (n * 32 + sw) * 16u, g_Whb + (size_t)n * HH + c * 8);
        }
        cpcommit(); cpwait<0>();
        __syncthreads();

        float acc[2][4];
#pragma unroll
        for (int a = 0; a < 2; a++)
#pragma unroll
            for (int c = 0; c < 4; c++) acc[a][c] = 0.0f;

#pragma unroll
        for (int ks = 0; ks < 16; ks++) {
            int m  = w * 16 + (L & 15);
            int ck = ks * 2 + (L >> 4);
            unsigned base = (ck < 16) ? b0a : b1a;
            int c2 = ck & 15;
            int sw = (c2 & 8) | ((c2 & 7) ^ (m & 7));
            unsigned a0, a1, a2, a3;
            ldm4(base + (m * 16 + sw) * 16u, a0, a1, a2, a3);
            int n   = (L & 7) + ((L >> 4) << 3);
            int ckb = ks * 2 + ((L >> 3) & 1);
            int swb = (ckb & 24) | ((ckb & 7) ^ (n & 7));
            unsigned b0, b1, b2, b3;
            ldm4(whaddr + (n * 32 + swb) * 16u, b0, b1, b2, b3);
            mma_bf16(acc[0], a0, a1, a2, a3, b0, b1);
            mma_bf16(acc[1], a0, a1, a2, a3, b2, b3);
        }

        const int g = L >> 2, q2 = (L & 3) * 2;
        float s = 0.0f;
#pragma unroll
        for (int nt = 0; nt < 2; nt++) {
            int n = nt * 8 + q2;
            float b0 = __ldg(&bh[n]), b1 = __ldg(&bh[n + 1]);
#pragma unroll
            for (int h = 0; h < 2; h++) {
                int m = w * 16 + g + 8 * h;
                const float* ar = action + (size_t)(r0 + m) * AA + n;
                float t0 = tanhf(acc[nt][2 * h + 0] + b0) - __ldg(&ar[0]);
                float t1 = tanhf(acc[nt][2 * h + 1] + b1) - __ldg(&ar[1]);
                s += t0 * t0 + t1 * t1;
            }
        }
        block_reduce_add_to(s, &g_sums[1]);
    }

    // ---- fused finalize ----
    if (tid == 0) {
        __threadfence();
        unsigned t = atomicAdd(&g_ticket, 1u);
        if (t == gridDim.x - 1) {
            double vq  = g_sums[0] / ((double)BB * (double)DD);
            double rec = g_sums[1] / ((double)BB * (double)AA);
            out[0] = (float)(rec + 1.25 * vq);
        }
    }
}

// ---------------------------------------------------------------------------
extern "C" void kernel_launch(void* const* d_in, const int* in_sizes, int n_in,
                              void* d_out, int out_size) {
    const float* action = (const float*)d_in[0];
    const float* We1    = (const float*)d_in[1];
    const float* be1    = (const float*)d_in[2];
    const float* We2    = (const float*)d_in[3];
    const float* be2    = (const float*)d_in[4];
    const float* We3    = (const float*)d_in[5];
    const float* be3    = (const float*)d_in[6];
    const float* E      = (const float*)d_in[7];
    const float* Wd1    = (const float*)d_in[8];
    const float* bd1    = (const float*)d_in[9];
    const float* Wd2    = (const float*)d_in[10];
    const float* bd2    = (const float*)d_in[11];
    const float* Wh     = (const float*)d_in[12];
    const float* bh     = (const float*)d_in[13];
    float* out = (float*)d_out;

    cudaFuncSetAttribute((const void*)mega_kernel,
                         cudaFuncAttributeMaxDynamicSharedMemorySize, SMEM_TOTAL);

    prep_kernel<<<464, 256>>>((const float4*)We1, (const float4*)We2,
                              (const float4*)We3, (const float4*)Wd1,
                              (const float4*)Wd2, (const float4*)Wh,
                              (const float4*)E, E);
    mega_kernel<<<BB / 128, 256, SMEM_TOTAL>>>(action, be1, be2, be3, E,
                                               bd1, bd2, bh, out);
}